// round 7
// baseline (speedup 1.0000x reference)
#include <cuda_runtime.h>
#include <cuda_bf16.h>
#include <cuda_fp16.h>
#include <cstdint>

#define NNODES 100000
#define NEDGES 1600000
#define FEAT   128

// -------- scratch (static device globals; allocation-free per harness rules) ----
__device__ __align__(16) float  g_self[NNODES * FEAT];
__device__ __align__(16) __half g_msg [NNODES * FEAT];   // fp16: only feeds mean-agg
__device__ __align__(16) float  g_h   [NNODES * FEAT];
__device__ int   g_deg [NNODES];
__device__ int   g_row_start[NNODES + 1];
__device__ int   g_csr[NEDGES];
// fp16 split weights, pre-transposed to [layer][n(0..255)][k(0..127)]
__device__ __align__(16) __half g_B0[2 * 256 * 128];   // hi
__device__ __align__(16) __half g_B1[2 * 256 * 128];   // lo (residual)

// ================================ helpers =======================================
__device__ __forceinline__ uint32_t sm_u32(const void* p) {
    uint32_t a;
    asm("{ .reg .u64 t; cvta.to.shared.u64 t, %1; cvt.u32.u64 %0, t; }"
        : "=r"(a) : "l"(p));
    return a;
}
__device__ __forceinline__ void ldsm_x4(uint32_t* r, uint32_t addr) {
    asm volatile("ldmatrix.sync.aligned.m8n8.x4.shared.b16 {%0,%1,%2,%3}, [%4];"
                 : "=r"(r[0]), "=r"(r[1]), "=r"(r[2]), "=r"(r[3]) : "r"(addr));
}
__device__ __forceinline__ void mma16816(float* c, const uint32_t* a,
                                         uint32_t b0, uint32_t b1) {
    asm volatile("mma.sync.aligned.m16n8k16.row.col.f32.f16.f16.f32 "
                 "{%0,%1,%2,%3}, {%4,%5,%6,%7}, {%8,%9}, {%0,%1,%2,%3};"
                 : "+f"(c[0]), "+f"(c[1]), "+f"(c[2]), "+f"(c[3])
                 : "r"(a[0]), "r"(a[1]), "r"(a[2]), "r"(a[3]), "r"(b0), "r"(b1));
}

// ============================= weight prep (once) ===============================
// g_B*[layer][n][k]: n<128 -> W[0] col n ; n>=128 -> W[1] col n-128 ; transposed.
// hi = fp16(w), lo = fp16(w - hi)  (B fully corrected by the 2nd chain)
__global__ void wprep_kernel(const float* __restrict__ W_in,
                             const float* __restrict__ W_out) {
    int idx = blockIdx.x * blockDim.x + threadIdx.x;
    if (idx >= 2 * 256 * 128) return;
    int layer = idx >> 15;
    int n = (idx >> 7) & 255;
    int k = idx & 127;
    const float* W = (layer ? W_out : W_in) + ((n >= 128) ? 128 * 128 : 0);
    float w = W[k * 128 + (n & 127)];
    __half w0 = __float2half_rn(w);
    __half w1 = __float2half_rn(w - __half2float(w0));
    g_B0[idx] = w0;
    g_B1[idx] = w1;
}

// =============================== CSR build ======================================
__global__ void zero_int_kernel(int* __restrict__ a, int n) {
    int i = blockIdx.x * blockDim.x + threadIdx.x;
    if (i < n) a[i] = 0;
}
__global__ void deg_kernel(const int* __restrict__ dst, int E) {
    int e = blockIdx.x * blockDim.x + threadIdx.x;
    if (e < E) atomicAdd(&g_deg[dst[e]], 1);
}
__global__ void scan_kernel(int n) {
    __shared__ int part[1024];
    const int T = 1024;
    int tid = threadIdx.x;
    int chunk = (n + T - 1) / T;
    int b = tid * chunk, e = min(b + chunk, n);
    int s = 0;
    for (int i = b; i < e; ++i) s += g_deg[i];
    part[tid] = s;
    __syncthreads();
    if (tid == 0) {
        int run = 0;
        for (int i = 0; i < T; ++i) { int t = part[i]; part[i] = run; run += t; }
    }
    __syncthreads();
    int run = part[tid];
    for (int i = b; i < e; ++i) { g_row_start[i] = run; run += g_deg[i]; }
    if (e == n) g_row_start[n] = run;
}
__global__ void fill_kernel(const int* __restrict__ src,
                            const int* __restrict__ dst, int E) {
    int e = blockIdx.x * blockDim.x + threadIdx.x;
    if (e < E) {
        int d = dst[e];
        int slot = g_row_start[d] + atomicSub(&g_deg[d], 1) - 1;
        g_csr[slot] = src[e];
    }
}

// ============== mma.sync dual GEMM (fp16, 2 chains: Ahi*Bhi + Ahi*Blo) ==========
// D[128][256] = X[128,128] @ [Wa | Wb]; B split corrects weight quantization,
// A residual (2^-11) dropped -> ~2e-4 per half per layer (empirically anchored).
// out_self fp32 ; out_msg fp16
#define GT 512
#define SM_AHI 0                 // 32 KB (fp16 A, hi only)
#define SM_BHI 32768             // 64 KB
#define SM_BLO 98304             // 64 KB
#define SMEM_TOTAL_GEMM 163840

__global__ __launch_bounds__(GT, 1)
void mma_gemm_kernel(const float* __restrict__ feat,
                     const __half* __restrict__ Bg0,
                     const __half* __restrict__ Bg1,
                     float* __restrict__ out_self,
                     __half* __restrict__ out_msg,
                     int nrows)
{
    extern __shared__ char smc[];
    const int tid = threadIdx.x;
    const uint32_t sb = sm_u32(smc);
    const int row0 = blockIdx.x * 128;

    // ---- B tiles: 256 rows x 16 chunks of 16B, swizzled
    for (int i = tid; i < 4096; i += GT) {
        int n = i >> 4, ch = i & 15;
        uint4 v0 = *(const uint4*)(Bg0 + n * 128 + ch * 8);
        uint4 v1 = *(const uint4*)(Bg1 + n * 128 + ch * 8);
        uint32_t off = n * 256 + ((ch ^ (n & 7)) << 4);
        *(uint4*)(smc + SM_BHI + off) = v0;
        *(uint4*)(smc + SM_BLO + off) = v1;
    }
    // ---- A tile: 128 rows x 16 chunks; fp32 -> fp16
    for (int i = tid; i < 2048; i += GT) {
        int r = i >> 4, ch = i & 15;
        int row = row0 + r;
        float4 u = make_float4(0.f, 0.f, 0.f, 0.f), v = u;
        if (row < nrows) {
            u = ((const float4*)feat)[row * 32 + ch * 2];
            v = ((const float4*)feat)[row * 32 + ch * 2 + 1];
        }
        uint4 h4;
        __half2 t;
        t = __floats2half2_rn(u.x, u.y); h4.x = *(uint32_t*)&t;
        t = __floats2half2_rn(u.z, u.w); h4.y = *(uint32_t*)&t;
        t = __floats2half2_rn(v.x, v.y); h4.z = *(uint32_t*)&t;
        t = __floats2half2_rn(v.z, v.w); h4.w = *(uint32_t*)&t;
        uint32_t off = r * 256 + ((ch ^ (r & 7)) << 4);
        *(uint4*)(smc + SM_AHI + off) = h4;
    }
    __syncthreads();

    const int wid = tid >> 5, lane = tid & 31;
    const int mw = wid & 3;          // M block: 32 rows
    const int nw = wid >> 2;         // N block: 64 cols
    const int s3 = lane & 7, sel = lane >> 3;

    float acc[2][8][4];
    #pragma unroll
    for (int a = 0; a < 2; ++a)
        #pragma unroll
        for (int b = 0; b < 8; ++b)
            #pragma unroll
            for (int c = 0; c < 4; ++c) acc[a][b][c] = 0.f;

    #pragma unroll
    for (int ks = 0; ks < 8; ++ks) {
        uint32_t ahi[2][4];
        #pragma unroll
        for (int mt = 0; mt < 2; ++mt) {
            int r = mw * 32 + mt * 16 + s3 + ((sel & 1) << 3);
            int ch = 2 * ks + (sel >> 1);
            uint32_t off = r * 256 + ((ch ^ (r & 7)) << 4);
            ldsm_x4(ahi[mt], sb + SM_AHI + off);
        }
        #pragma unroll
        for (int jp = 0; jp < 4; ++jp) {
            int r = nw * 64 + jp * 16 + s3 + ((sel >> 1) << 3);
            int ch = 2 * ks + (sel & 1);
            uint32_t off = r * 256 + ((ch ^ (r & 7)) << 4);
            uint32_t bhi[4], blo[4];
            ldsm_x4(bhi, sb + SM_BHI + off);
            ldsm_x4(blo, sb + SM_BLO + off);
            #pragma unroll
            for (int t = 0; t < 2; ++t) {
                int nt = jp * 2 + t;
                #pragma unroll
                for (int mt = 0; mt < 2; ++mt) {
                    mma16816(acc[mt][nt], ahi[mt], bhi[2*t], bhi[2*t+1]);
                    mma16816(acc[mt][nt], ahi[mt], blo[2*t], blo[2*t+1]);
                }
            }
        }
    }

    // ---- epilogue: nw 0,1 -> out_self (fp32) ; nw 2,3 -> out_msg (fp16)
    const int g = lane >> 2, tq = lane & 3;
    const int colhalf = (nw & 1) * 64;
    const bool self_half = (nw < 2);
    #pragma unroll
    for (int mt = 0; mt < 2; ++mt) {
        int rr = row0 + mw * 32 + mt * 16 + g;
        #pragma unroll
        for (int nt = 0; nt < 8; ++nt) {
            int col = colhalf + nt * 8 + 2 * tq;
            if (self_half) {
                if (rr < nrows)
                    *(float2*)(out_self + (size_t)rr * 128 + col) =
                        make_float2(acc[mt][nt][0], acc[mt][nt][1]);
                if (rr + 8 < nrows)
                    *(float2*)(out_self + (size_t)(rr + 8) * 128 + col) =
                        make_float2(acc[mt][nt][2], acc[mt][nt][3]);
            } else {
                if (rr < nrows)
                    *(__half2*)(out_msg + (size_t)rr * 128 + col) =
                        __floats2half2_rn(acc[mt][nt][0], acc[mt][nt][1]);
                if (rr + 8 < nrows)
                    *(__half2*)(out_msg + (size_t)(rr + 8) * 128 + col) =
                        __floats2half2_rn(acc[mt][nt][2], acc[mt][nt][3]);
            }
        }
    }
}

// ------------------- CSR gather-mean (fp16 msg) + combine (+ReLU) ---------------
__global__ void agg_csr_kernel(const __half* __restrict__ msg,
                               const float* __restrict__ self,
                               float* __restrict__ out,
                               int N, int relu)
{
    int w = (blockIdx.x * blockDim.x + threadIdx.x) >> 5;
    if (w >= N) return;
    int lane = threadIdx.x & 31;

    int beg = __ldg(&g_row_start[w]);
    int end = __ldg(&g_row_start[w + 1]);

    float4 a0 = make_float4(0.f, 0.f, 0.f, 0.f);
    float4 a1 = make_float4(0.f, 0.f, 0.f, 0.f);
    float4 a2 = make_float4(0.f, 0.f, 0.f, 0.f);
    float4 a3 = make_float4(0.f, 0.f, 0.f, 0.f);

    int e = beg;
    for (; e + 4 <= end; e += 4) {
        int s0 = __ldg(&g_csr[e]);
        int s1 = __ldg(&g_csr[e + 1]);
        int s2 = __ldg(&g_csr[e + 2]);
        int s3 = __ldg(&g_csr[e + 3]);
        uint2 u0 = __ldg((const uint2*)(msg + (size_t)s0 * 128) + lane);
        uint2 u1 = __ldg((const uint2*)(msg + (size_t)s1 * 128) + lane);
        uint2 u2 = __ldg((const uint2*)(msg + (size_t)s2 * 128) + lane);
        uint2 u3 = __ldg((const uint2*)(msg + (size_t)s3 * 128) + lane);
        float2 f;
        f = __half22float2(*(__half2*)&u0.x); a0.x += f.x; a0.y += f.y;
        f = __half22float2(*(__half2*)&u0.y); a0.z += f.x; a0.w += f.y;
        f = __half22float2(*(__half2*)&u1.x); a1.x += f.x; a1.y += f.y;
        f = __half22float2(*(__half2*)&u1.y); a1.z += f.x; a1.w += f.y;
        f = __half22float2(*(__half2*)&u2.x); a2.x += f.x; a2.y += f.y;
        f = __half22float2(*(__half2*)&u2.y); a2.z += f.x; a2.w += f.y;
        f = __half22float2(*(__half2*)&u3.x); a3.x += f.x; a3.y += f.y;
        f = __half22float2(*(__half2*)&u3.y); a3.z += f.x; a3.w += f.y;
    }
    for (; e < end; ++e) {
        int s0 = __ldg(&g_csr[e]);
        uint2 u0 = __ldg((const uint2*)(msg + (size_t)s0 * 128) + lane);
        float2 f;
        f = __half22float2(*(__half2*)&u0.x); a0.x += f.x; a0.y += f.y;
        f = __half22float2(*(__half2*)&u0.y); a0.z += f.x; a0.w += f.y;
    }

    a0.x += a1.x; a0.y += a1.y; a0.z += a1.z; a0.w += a1.w;
    a2.x += a3.x; a2.y += a3.y; a2.z += a3.z; a2.w += a3.w;
    a0.x += a2.x; a0.y += a2.y; a0.z += a2.z; a0.w += a2.w;

    float inv = 1.0f / fmaxf((float)(end - beg), 1.0f);
    float4 sf = ((const float4*)self)[w * 32 + lane];
    float4 o;
    o.x = fmaf(a0.x, inv, sf.x);
    o.y = fmaf(a0.y, inv, sf.y);
    o.z = fmaf(a0.z, inv, sf.z);
    o.w = fmaf(a0.w, inv, sf.w);
    if (relu) {
        o.x = fmaxf(o.x, 0.f); o.y = fmaxf(o.y, 0.f);
        o.z = fmaxf(o.z, 0.f); o.w = fmaxf(o.w, 0.f);
    }
    ((float4*)out)[w * 32 + lane] = o;
}

// --------------------------------------------------------------------------------
extern "C" void kernel_launch(void* const* d_in, const int* in_sizes, int n_in,
                              void* d_out, int out_size)
{
    const float* x     = (const float*)d_in[0];
    const float* W_in  = (const float*)d_in[1];
    const float* W_out = (const float*)d_in[2];
    const int*   src   = (const int*)d_in[3];
    const int*   dst   = (const int*)d_in[4];
    float*       out   = (float*)d_out;

    const int N = in_sizes[0] / FEAT;
    const int E = in_sizes[3];

    float *p_self, *p_h;
    __half *p_msg;
    int *p_deg;
    __half *p_B0, *p_B1;
    cudaGetSymbolAddress((void**)&p_self, g_self);
    cudaGetSymbolAddress((void**)&p_msg,  g_msg);
    cudaGetSymbolAddress((void**)&p_h,    g_h);
    cudaGetSymbolAddress((void**)&p_deg,  g_deg);
    cudaGetSymbolAddress((void**)&p_B0,   g_B0);
    cudaGetSymbolAddress((void**)&p_B1,   g_B1);

    static bool s_init = false;
    static cudaStream_t s2 = 0;
    static cudaEvent_t evF = 0, evJ = 0;
    if (!s_init) {
        cudaFuncSetAttribute(mma_gemm_kernel,
                             cudaFuncAttributeMaxDynamicSharedMemorySize,
                             SMEM_TOTAL_GEMM);
        if (cudaStreamCreateWithFlags(&s2, cudaStreamNonBlocking) != cudaSuccess)
            s2 = 0;
        cudaEventCreateWithFlags(&evF, cudaEventDisableTiming);
        cudaEventCreateWithFlags(&evJ, cudaEventDisableTiming);
        s_init = true;
    }

    const int ggrid = (N + 127) / 128;
    const int agrid = (N * 32 + 255) / 256;
    const int egrid = (E + 255) / 256;

    // ---- fork: CSR build on side stream; GEMM is launch #4 (ncu capture slot) ----
    cudaEventRecord(evF, 0);
    cudaStreamWaitEvent(s2, evF, 0);
    zero_int_kernel<<<(N + 255) / 256, 256, 0, s2>>>(p_deg, N);          // #1
    wprep_kernel<<<(2 * 256 * 128 + 255) / 256, 256>>>(W_in, W_out);     // #2
    deg_kernel<<<egrid, 256, 0, s2>>>(dst, E);                           // #3
    mma_gemm_kernel<<<ggrid, GT, SMEM_TOTAL_GEMM>>>(                     // #4
        x, p_B0, p_B1, p_self, p_msg, N);
    scan_kernel<<<1, 1024, 0, s2>>>(N);                                  // #5
    fill_kernel<<<egrid, 256, 0, s2>>>(src, dst, E);                     // #6
    cudaEventRecord(evJ, s2);

    // ---- join: aggregation needs the CSR + layer-1 GEMM ----
    cudaStreamWaitEvent(0, evJ, 0);
    agg_csr_kernel<<<agrid, 256>>>(p_msg, p_self, p_h, N, 1);

    // ---- layer 2 ----
    mma_gemm_kernel<<<ggrid, GT, SMEM_TOTAL_GEMM>>>(
        p_h, p_B0 + 256 * 128, p_B1 + 256 * 128, p_self, p_msg, N);
    agg_csr_kernel<<<agrid, 256>>>(p_msg, p_self, out, N, 0);
}

// round 8
// speedup vs baseline: 1.0255x; 1.0255x over previous
#include <cuda_runtime.h>
#include <cuda_bf16.h>
#include <cuda_fp16.h>
#include <cstdint>

#define NNODES 100000
#define NEDGES 1600000
#define FEAT   128

// -------- scratch (static device globals; allocation-free per harness rules) ----
__device__ __align__(16) float  g_self [NNODES * FEAT];  // layer1 self (fp32)
__device__ __align__(16) __half g_msg  [NNODES * FEAT];  // layer1 msg  (fp16)
__device__ __align__(16) __half g_hh   [NNODES * FEAT];  // hidden h    (fp16)
__device__ __align__(16) float  g_self2[NNODES * FEAT];  // layer2 self (fp32)
__device__ __align__(16) __half g_msg2 [NNODES * FEAT];  // layer2 msg  (fp16)
__device__ int g_deg[NNODES];
__device__ int g_row_start[NNODES + 1];
__device__ int g_csr[NEDGES];
// fp16 split weights, pre-transposed to [layer][n(0..255)][k(0..127)]
__device__ __align__(16) __half g_B0[2 * 256 * 128];   // hi
__device__ __align__(16) __half g_B1[2 * 256 * 128];   // lo (residual)

// ================================ helpers =======================================
__device__ __forceinline__ uint32_t sm_u32(const void* p) {
    uint32_t a;
    asm("{ .reg .u64 t; cvta.to.shared.u64 t, %1; cvt.u32.u64 %0, t; }"
        : "=r"(a) : "l"(p));
    return a;
}
__device__ __forceinline__ void ldsm_x4(uint32_t* r, uint32_t addr) {
    asm volatile("ldmatrix.sync.aligned.m8n8.x4.shared.b16 {%0,%1,%2,%3}, [%4];"
                 : "=r"(r[0]), "=r"(r[1]), "=r"(r[2]), "=r"(r[3]) : "r"(addr));
}
__device__ __forceinline__ void mma16816(float* c, const uint32_t* a,
                                         uint32_t b0, uint32_t b1) {
    asm volatile("mma.sync.aligned.m16n8k16.row.col.f32.f16.f16.f32 "
                 "{%0,%1,%2,%3}, {%4,%5,%6,%7}, {%8,%9}, {%0,%1,%2,%3};"
                 : "+f"(c[0]), "+f"(c[1]), "+f"(c[2]), "+f"(c[3])
                 : "r"(a[0]), "r"(a[1]), "r"(a[2]), "r"(a[3]), "r"(b0), "r"(b1));
}

// ============================= weight prep (once) ===============================
__global__ void wprep_kernel(const float* __restrict__ W_in,
                             const float* __restrict__ W_out) {
    int idx = blockIdx.x * blockDim.x + threadIdx.x;
    if (idx >= 2 * 256 * 128) return;
    int layer = idx >> 15;
    int n = (idx >> 7) & 255;
    int k = idx & 127;
    const float* W = (layer ? W_out : W_in) + ((n >= 128) ? 128 * 128 : 0);
    float w = W[k * 128 + (n & 127)];
    __half w0 = __float2half_rn(w);
    __half w1 = __float2half_rn(w - __half2float(w0));
    g_B0[idx] = w0;
    g_B1[idx] = w1;
}

// =============================== CSR build ======================================
__global__ void zero_int_kernel(int* __restrict__ a, int n) {
    int i = blockIdx.x * blockDim.x + threadIdx.x;
    if (i < n) a[i] = 0;
}
__global__ void deg_kernel(const int* __restrict__ dst, int E) {
    int e = blockIdx.x * blockDim.x + threadIdx.x;
    if (e < E) atomicAdd(&g_deg[dst[e]], 1);
}
__global__ void scan_kernel(int n) {
    __shared__ int part[1024];
    const int T = 1024;
    int tid = threadIdx.x;
    int chunk = (n + T - 1) / T;
    int b = tid * chunk, e = min(b + chunk, n);
    int s = 0;
    for (int i = b; i < e; ++i) s += g_deg[i];
    part[tid] = s;
    __syncthreads();
    if (tid == 0) {
        int run = 0;
        for (int i = 0; i < T; ++i) { int t = part[i]; part[i] = run; run += t; }
    }
    __syncthreads();
    int run = part[tid];
    for (int i = b; i < e; ++i) { g_row_start[i] = run; run += g_deg[i]; }
    if (e == n) g_row_start[n] = run;
}
__global__ void fill_kernel(const int* __restrict__ src,
                            const int* __restrict__ dst, int E) {
    int e = blockIdx.x * blockDim.x + threadIdx.x;
    if (e < E) {
        int d = dst[e];
        int slot = g_row_start[d] + atomicSub(&g_deg[d], 1) - 1;
        g_csr[slot] = src[e];
    }
}

// ====== mma.sync dual GEMM (fp16; self: Ahi*Bhi+Ahi*Blo, msg: Ahi*Bhi only) =====
// A source: fp32 (layer 1) or fp16 (layer 2, pre-rounded h — bit-identical).
#define GT 512
#define SM_AHI 0                 // 32 KB
#define SM_BHI 32768             // 64 KB (256 rows)
#define SM_BLO 98304             // 32 KB (self half only, 128 rows)
#define SMEM_TOTAL_GEMM 131072

__global__ __launch_bounds__(GT, 1)
void mma_gemm_kernel(const float* __restrict__ featf,
                     const __half* __restrict__ feath,
                     const __half* __restrict__ Bg0,
                     const __half* __restrict__ Bg1,
                     float* __restrict__ out_self,
                     __half* __restrict__ out_msg,
                     int row_base, int nrows)
{
    extern __shared__ char smc[];
    const int tid = threadIdx.x;
    const uint32_t sb = sm_u32(smc);
    const int row0 = row_base + blockIdx.x * 128;

    // ---- BHI: 256 rows x 16 chunks of 16B, swizzled
    for (int i = tid; i < 4096; i += GT) {
        int n = i >> 4, ch = i & 15;
        uint4 v0 = *(const uint4*)(Bg0 + n * 128 + ch * 8);
        uint32_t off = n * 256 + ((ch ^ (n & 7)) << 4);
        *(uint4*)(smc + SM_BHI + off) = v0;
    }
    // ---- BLO: self half only (rows 0..127)
    for (int i = tid; i < 2048; i += GT) {
        int n = i >> 4, ch = i & 15;
        uint4 v1 = *(const uint4*)(Bg1 + n * 128 + ch * 8);
        uint32_t off = n * 256 + ((ch ^ (n & 7)) << 4);
        *(uint4*)(smc + SM_BLO + off) = v1;
    }
    // ---- A tile: 128 rows x 16 chunks (fp16 smem); source fp32 or fp16
    for (int i = tid; i < 2048; i += GT) {
        int r = i >> 4, ch = i & 15;
        int row = row0 + r;
        uint4 h4 = make_uint4(0, 0, 0, 0);
        if (row < nrows) {
            if (feath) {
                h4 = ((const uint4*)(feath + (size_t)row * 128))[ch];
            } else {
                float4 u = ((const float4*)featf)[row * 32 + ch * 2];
                float4 v = ((const float4*)featf)[row * 32 + ch * 2 + 1];
                __half2 t;
                t = __floats2half2_rn(u.x, u.y); h4.x = *(uint32_t*)&t;
                t = __floats2half2_rn(u.z, u.w); h4.y = *(uint32_t*)&t;
                t = __floats2half2_rn(v.x, v.y); h4.z = *(uint32_t*)&t;
                t = __floats2half2_rn(v.z, v.w); h4.w = *(uint32_t*)&t;
            }
        }
        uint32_t off = r * 256 + ((ch ^ (r & 7)) << 4);
        *(uint4*)(smc + SM_AHI + off) = h4;
    }
    __syncthreads();

    const int wid = tid >> 5, lane = tid & 31;
    const int mw = wid & 3;          // M block: 32 rows
    const int nw = wid >> 2;         // N block: 64 cols
    const bool self_half = (nw < 2);
    const int s3 = lane & 7, sel = lane >> 3;

    float acc[2][8][4];
    #pragma unroll
    for (int a = 0; a < 2; ++a)
        #pragma unroll
        for (int b = 0; b < 8; ++b)
            #pragma unroll
            for (int c = 0; c < 4; ++c) acc[a][b][c] = 0.f;

    #pragma unroll
    for (int ks = 0; ks < 8; ++ks) {
        uint32_t ahi[2][4];
        #pragma unroll
        for (int mt = 0; mt < 2; ++mt) {
            int r = mw * 32 + mt * 16 + s3 + ((sel & 1) << 3);
            int ch = 2 * ks + (sel >> 1);
            uint32_t off = r * 256 + ((ch ^ (r & 7)) << 4);
            ldsm_x4(ahi[mt], sb + SM_AHI + off);
        }
        #pragma unroll
        for (int jp = 0; jp < 4; ++jp) {
            int r = nw * 64 + jp * 16 + s3 + ((sel >> 1) << 3);
            int ch = 2 * ks + (sel & 1);
            uint32_t off = r * 256 + ((ch ^ (r & 7)) << 4);
            uint32_t bhi[4], blo[4];
            ldsm_x4(bhi, sb + SM_BHI + off);
            if (self_half) ldsm_x4(blo, sb + SM_BLO + off);
            #pragma unroll
            for (int t = 0; t < 2; ++t) {
                int nt = jp * 2 + t;
                #pragma unroll
                for (int mt = 0; mt < 2; ++mt) {
                    mma16816(acc[mt][nt], ahi[mt], bhi[2*t], bhi[2*t+1]);
                    if (self_half)
                        mma16816(acc[mt][nt], ahi[mt], blo[2*t], blo[2*t+1]);
                }
            }
        }
    }

    // ---- epilogue
    const int g = lane >> 2, tq = lane & 3;
    const int colhalf = (nw & 1) * 64;
    #pragma unroll
    for (int mt = 0; mt < 2; ++mt) {
        int rr = row0 + mw * 32 + mt * 16 + g;
        #pragma unroll
        for (int nt = 0; nt < 8; ++nt) {
            int col = colhalf + nt * 8 + 2 * tq;
            if (self_half) {
                if (rr < nrows)
                    *(float2*)(out_self + (size_t)rr * 128 + col) =
                        make_float2(acc[mt][nt][0], acc[mt][nt][1]);
                if (rr + 8 < nrows)
                    *(float2*)(out_self + (size_t)(rr + 8) * 128 + col) =
                        make_float2(acc[mt][nt][2], acc[mt][nt][3]);
            } else {
                if (rr < nrows)
                    *(__half2*)(out_msg + (size_t)rr * 128 + col) =
                        __floats2half2_rn(acc[mt][nt][0], acc[mt][nt][1]);
                if (rr + 8 < nrows)
                    *(__half2*)(out_msg + (size_t)(rr + 8) * 128 + col) =
                        __floats2half2_rn(acc[mt][nt][2], acc[mt][nt][3]);
            }
        }
    }
}

// ------- CSR gather-mean (fp16 msg) + combine (+ReLU); fp32 or fp16 output ------
__global__ void agg_csr_kernel(const __half* __restrict__ msg,
                               const float* __restrict__ self,
                               float* __restrict__ outf,
                               __half* __restrict__ outh,
                               int node_base, int node_end, int relu)
{
    int w = node_base + ((blockIdx.x * blockDim.x + threadIdx.x) >> 5);
    if (w >= node_end) return;
    int lane = threadIdx.x & 31;

    int beg = __ldg(&g_row_start[w]);
    int end = __ldg(&g_row_start[w + 1]);

    float4 a0 = make_float4(0.f, 0.f, 0.f, 0.f);
    float4 a1 = make_float4(0.f, 0.f, 0.f, 0.f);
    float4 a2 = make_float4(0.f, 0.f, 0.f, 0.f);
    float4 a3 = make_float4(0.f, 0.f, 0.f, 0.f);

    int e = beg;
    for (; e + 8 <= end; e += 8) {                 // 8 loads in flight
        int s[8];
        #pragma unroll
        for (int j = 0; j < 8; ++j) s[j] = __ldg(&g_csr[e + j]);
        uint2 u[8];
        #pragma unroll
        for (int j = 0; j < 8; ++j)
            u[j] = __ldg((const uint2*)(msg + (size_t)s[j] * 128) + lane);
        #pragma unroll
        for (int j = 0; j < 8; ++j) {
            float2 f0 = __half22float2(*(__half2*)&u[j].x);
            float2 f1 = __half22float2(*(__half2*)&u[j].y);
            float4* a = (j & 2) ? ((j & 1) ? &a3 : &a2) : ((j & 1) ? &a1 : &a0);
            a->x += f0.x; a->y += f0.y; a->z += f1.x; a->w += f1.y;
        }
    }
    for (; e + 2 <= end; e += 2) {
        int s0 = __ldg(&g_csr[e]), s1 = __ldg(&g_csr[e + 1]);
        uint2 u0 = __ldg((const uint2*)(msg + (size_t)s0 * 128) + lane);
        uint2 u1 = __ldg((const uint2*)(msg + (size_t)s1 * 128) + lane);
        float2 f;
        f = __half22float2(*(__half2*)&u0.x); a0.x += f.x; a0.y += f.y;
        f = __half22float2(*(__half2*)&u0.y); a0.z += f.x; a0.w += f.y;
        f = __half22float2(*(__half2*)&u1.x); a1.x += f.x; a1.y += f.y;
        f = __half22float2(*(__half2*)&u1.y); a1.z += f.x; a1.w += f.y;
    }
    if (e < end) {
        int s0 = __ldg(&g_csr[e]);
        uint2 u0 = __ldg((const uint2*)(msg + (size_t)s0 * 128) + lane);
        float2 f;
        f = __half22float2(*(__half2*)&u0.x); a0.x += f.x; a0.y += f.y;
        f = __half22float2(*(__half2*)&u0.y); a0.z += f.x; a0.w += f.y;
    }

    a0.x += a1.x; a0.y += a1.y; a0.z += a1.z; a0.w += a1.w;
    a2.x += a3.x; a2.y += a3.y; a2.z += a3.z; a2.w += a3.w;
    a0.x += a2.x; a0.y += a2.y; a0.z += a2.z; a0.w += a2.w;

    float inv = 1.0f / fmaxf((float)(end - beg), 1.0f);
    float4 sf = ((const float4*)self)[w * 32 + lane];
    float4 o;
    o.x = fmaf(a0.x, inv, sf.x);
    o.y = fmaf(a0.y, inv, sf.y);
    o.z = fmaf(a0.z, inv, sf.z);
    o.w = fmaf(a0.w, inv, sf.w);
    if (relu) {
        o.x = fmaxf(o.x, 0.f); o.y = fmaxf(o.y, 0.f);
        o.z = fmaxf(o.z, 0.f); o.w = fmaxf(o.w, 0.f);
    }
    if (outf) {
        ((float4*)outf)[w * 32 + lane] = o;
    } else {
        uint2 p;
        __half2 t;
        t = __floats2half2_rn(o.x, o.y); p.x = *(uint32_t*)&t;
        t = __floats2half2_rn(o.z, o.w); p.y = *(uint32_t*)&t;
        ((uint2*)outh)[w * 32 + lane] = p;
    }
}

// --------------------------------------------------------------------------------
extern "C" void kernel_launch(void* const* d_in, const int* in_sizes, int n_in,
                              void* d_out, int out_size)
{
    const float* x     = (const float*)d_in[0];
    const float* W_in  = (const float*)d_in[1];
    const float* W_out = (const float*)d_in[2];
    const int*   src   = (const int*)d_in[3];
    const int*   dst   = (const int*)d_in[4];
    float*       out   = (float*)d_out;

    const int N = in_sizes[0] / FEAT;
    const int E = in_sizes[3];
    const int Nh = ((N / 2 + 127) / 128) * 128;   // chunk boundary, mult of 128

    float *p_self, *p_self2;
    __half *p_msg, *p_msg2, *p_hh;
    int *p_deg;
    __half *p_B0, *p_B1;
    cudaGetSymbolAddress((void**)&p_self,  g_self);
    cudaGetSymbolAddress((void**)&p_self2, g_self2);
    cudaGetSymbolAddress((void**)&p_msg,   g_msg);
    cudaGetSymbolAddress((void**)&p_msg2,  g_msg2);
    cudaGetSymbolAddress((void**)&p_hh,    g_hh);
    cudaGetSymbolAddress((void**)&p_deg,   g_deg);
    cudaGetSymbolAddress((void**)&p_B0,    g_B0);
    cudaGetSymbolAddress((void**)&p_B1,    g_B1);

    static bool s_init = false;
    static cudaStream_t s2 = 0;
    static cudaEvent_t evF = 0, evJ = 0, evA0 = 0, evG0 = 0;
    if (!s_init) {
        cudaFuncSetAttribute(mma_gemm_kernel,
                             cudaFuncAttributeMaxDynamicSharedMemorySize,
                             SMEM_TOTAL_GEMM);
        if (cudaStreamCreateWithFlags(&s2, cudaStreamNonBlocking) != cudaSuccess)
            s2 = 0;
        cudaEventCreateWithFlags(&evF,  cudaEventDisableTiming);
        cudaEventCreateWithFlags(&evJ,  cudaEventDisableTiming);
        cudaEventCreateWithFlags(&evA0, cudaEventDisableTiming);
        cudaEventCreateWithFlags(&evG0, cudaEventDisableTiming);
        s_init = true;
    }

    const int egrid = (E + 255) / 256;
    const __half* B0L2 = p_B0 + 256 * 128;
    const __half* B1L2 = p_B1 + 256 * 128;

    auto agg_grid = [](int nodes) { return (nodes * 32 + 127) / 128; };
    auto gemm_grid = [](int rows) { return (rows + 127) / 128; };

    // ---- fork: CSR build on s2, overlapped with wprep + layer-1 GEMM ----
    cudaEventRecord(evF, 0);
    cudaStreamWaitEvent(s2, evF, 0);
    zero_int_kernel<<<(N + 255) / 256, 256, 0, s2>>>(p_deg, N);
    wprep_kernel<<<(2 * 256 * 128 + 255) / 256, 256>>>(W_in, W_out);
    deg_kernel<<<egrid, 256, 0, s2>>>(dst, E);
    mma_gemm_kernel<<<gemm_grid(N), GT, SMEM_TOTAL_GEMM>>>(
        x, nullptr, p_B0, p_B1, p_self, p_msg, 0, N);
    scan_kernel<<<1, 1024, 0, s2>>>(N);
    fill_kernel<<<egrid, 256, 0, s2>>>(src, dst, E);
    cudaEventRecord(evJ, s2);

    // ---- layer 1 aggregation, chunked; h stored fp16 ----
    cudaStreamWaitEvent(0, evJ, 0);
    agg_csr_kernel<<<agg_grid(Nh), 128>>>(p_msg, p_self, nullptr, p_hh, 0, Nh, 1);
    cudaEventRecord(evA0, 0);

    // gemm2 chunk0 on s2, concurrent with agg1 chunk1 on default
    cudaStreamWaitEvent(s2, evA0, 0);
    mma_gemm_kernel<<<gemm_grid(Nh), GT, SMEM_TOTAL_GEMM, s2>>>(
        nullptr, p_hh, B0L2, B1L2, p_self2, p_msg2, 0, N);
    cudaEventRecord(evG0, s2);

    agg_csr_kernel<<<agg_grid(N - Nh), 128>>>(p_msg, p_self, nullptr, p_hh, Nh, N, 1);
    mma_gemm_kernel<<<gemm_grid(N - Nh), GT, SMEM_TOTAL_GEMM>>>(
        nullptr, p_hh, B0L2, B1L2, p_self2, p_msg2, Nh, N);

    // ---- layer 2 aggregation (needs both gemm2 chunks) ----
    cudaStreamWaitEvent(0, evG0, 0);
    agg_csr_kernel<<<agg_grid(N), 128>>>(p_msg2, p_self2, out, nullptr, 0, N, 0);
}

// round 9
// speedup vs baseline: 1.2656x; 1.2342x over previous
#include <cuda_runtime.h>
#include <cuda_bf16.h>
#include <cuda_fp16.h>
#include <cstdint>

#define NNODES 100000
#define NEDGES 1600000
#define FEAT   128

// -------- scratch (static device globals; allocation-free per harness rules) ----
__device__ __align__(16) float  g_self [NNODES * FEAT];  // layer1 self (fp32)
__device__ __align__(16) __half g_msg  [NNODES * FEAT];  // layer1 msg  (fp16)
__device__ __align__(16) __half g_hh   [NNODES * FEAT];  // hidden h    (fp16)
__device__ __align__(16) float  g_self2[NNODES * FEAT];  // layer2 self (fp32)
__device__ __align__(16) __half g_msg2 [NNODES * FEAT];  // layer2 msg  (fp16)
__device__ __align__(16) __half g_xh   [NNODES * FEAT];  // x rounded to fp16
__device__ int g_deg[NNODES];
__device__ int g_row_start[NNODES + 1];
__device__ int g_csr[NEDGES];
// fp16 split weights, pre-transposed to [layer][n(0..255)][k(0..127)]
__device__ __align__(16) __half g_B0[2 * 256 * 128];   // hi
__device__ __align__(16) __half g_B1[2 * 256 * 128];   // lo (residual)

// ================================ helpers =======================================
__device__ __forceinline__ uint32_t sm_u32(const void* p) {
    uint32_t a;
    asm("{ .reg .u64 t; cvta.to.shared.u64 t, %1; cvt.u32.u64 %0, t; }"
        : "=r"(a) : "l"(p));
    return a;
}
__device__ __forceinline__ void ldsm_x4(uint32_t* r, uint32_t addr) {
    asm volatile("ldmatrix.sync.aligned.m8n8.x4.shared.b16 {%0,%1,%2,%3}, [%4];"
                 : "=r"(r[0]), "=r"(r[1]), "=r"(r[2]), "=r"(r[3]) : "r"(addr));
}
__device__ __forceinline__ void mma16816(float* c, const uint32_t* a,
                                         uint32_t b0, uint32_t b1) {
    asm volatile("mma.sync.aligned.m16n8k16.row.col.f32.f16.f16.f32 "
                 "{%0,%1,%2,%3}, {%4,%5,%6,%7}, {%8,%9}, {%0,%1,%2,%3};"
                 : "+f"(c[0]), "+f"(c[1]), "+f"(c[2]), "+f"(c[3])
                 : "r"(a[0]), "r"(a[1]), "r"(a[2]), "r"(a[3]), "r"(b0), "r"(b1));
}
__device__ __forceinline__ void cp16(uint32_t saddr, const void* g, int src_sz) {
    asm volatile("cp.async.cg.shared.global [%0], [%1], 16, %2;"
                 :: "r"(saddr), "l"(g), "r"(src_sz) : "memory");
}
__device__ __forceinline__ void cp_commit() {
    asm volatile("cp.async.commit_group;" ::: "memory");
}

// ============================= prep kernels (once) ==============================
__global__ void wprep_kernel(const float* __restrict__ W_in,
                             const float* __restrict__ W_out) {
    int idx = blockIdx.x * blockDim.x + threadIdx.x;
    if (idx >= 2 * 256 * 128) return;
    int layer = idx >> 15;
    int n = (idx >> 7) & 255;
    int k = idx & 127;
    const float* W = (layer ? W_out : W_in) + ((n >= 128) ? 128 * 128 : 0);
    float w = W[k * 128 + (n & 127)];
    __half w0 = __float2half_rn(w);
    __half w1 = __float2half_rn(w - __half2float(w0));
    g_B0[idx] = w0;
    g_B1[idx] = w1;
}
__global__ void xh_kernel(const float* __restrict__ x, int n4) {
    int i = blockIdx.x * blockDim.x + threadIdx.x;
    if (i >= n4) return;
    float4 v = ((const float4*)x)[i];
    __half2 t0 = __floats2half2_rn(v.x, v.y);
    __half2 t1 = __floats2half2_rn(v.z, v.w);
    uint2 p = make_uint2(*(uint32_t*)&t0, *(uint32_t*)&t1);
    ((uint2*)g_xh)[i] = p;
}

// =============================== CSR build ======================================
__global__ void zero_int_kernel(int* __restrict__ a, int n) {
    int i = blockIdx.x * blockDim.x + threadIdx.x;
    if (i < n) a[i] = 0;
}
__global__ void deg_kernel(const int* __restrict__ dst, int E) {
    int e = blockIdx.x * blockDim.x + threadIdx.x;
    if (e < E) atomicAdd(&g_deg[dst[e]], 1);
}
__global__ void scan_kernel(int n) {
    __shared__ int part[1024];
    const int T = 1024;
    int tid = threadIdx.x;
    int chunk = (n + T - 1) / T;
    int b = tid * chunk, e = min(b + chunk, n);
    int s = 0;
    for (int i = b; i < e; ++i) s += g_deg[i];
    part[tid] = s;
    __syncthreads();
    if (tid == 0) {
        int run = 0;
        for (int i = 0; i < T; ++i) { int t = part[i]; part[i] = run; run += t; }
    }
    __syncthreads();
    int run = part[tid];
    for (int i = b; i < e; ++i) { g_row_start[i] = run; run += g_deg[i]; }
    if (e == n) g_row_start[n] = run;
}
__global__ void fill_kernel(const int* __restrict__ src,
                            const int* __restrict__ dst, int E) {
    int e = blockIdx.x * blockDim.x + threadIdx.x;
    if (e < E) {
        int d = dst[e];
        int slot = g_row_start[d] + atomicSub(&g_deg[d], 1) - 1;
        g_csr[slot] = src[e];
    }
}

// ====== persistent mma.sync dual GEMM, cp.async double-buffered A ===============
// D[128][256] per tile = A[128,128] @ [Wa | Wb]
//   self half: Ahi*(Bhi+Blo) (2 chains) ; msg half: Ahi*Bhi (1 chain)
// B loaded ONCE per CTA (persistent grid = #SMs); A pipelined with cp.async.cg.
#define GT 512
#define SM_A0  0                 // 32 KB
#define SM_A1  32768             // 32 KB
#define SM_BHI 65536             // 64 KB (256 rows)
#define SM_BLO 131072            // 32 KB (self half only)
#define SMEM_TOTAL_GEMM 163840

__device__ __forceinline__ void prefetch_A(uint32_t sb, int buf,
                                           const __half* __restrict__ feath,
                                           int row0, int nrows) {
    const uint32_t base = sb + (buf ? SM_A1 : SM_A0);
    int idx = threadIdx.x;
    #pragma unroll
    for (int j = 0; j < 4; ++j, idx += GT) {      // 2048 chunks of 16B
        int r = idx >> 4, ch = idx & 15;
        int row = row0 + r;
        uint32_t off = r * 256 + ((ch ^ (r & 7)) << 4);
        cp16(base + off, feath + (size_t)row * 128 + ch * 8,
             (row < nrows) ? 16 : 0);
    }
}

__global__ __launch_bounds__(GT, 1)
void mma_gemm_kernel(const __half* __restrict__ feath,
                     const __half* __restrict__ Bg0,
                     const __half* __restrict__ Bg1,
                     float* __restrict__ out_self,
                     __half* __restrict__ out_msg,
                     int row_base, int nrows, int ntiles)
{
    extern __shared__ char smc[];
    const int tid = threadIdx.x;
    const uint32_t sb = sm_u32(smc);

    // ---- B tiles via cp.async (once per CTA)
    {
        int idx = tid;
        #pragma unroll
        for (int j = 0; j < 8; ++j, idx += GT) {  // BHI: 4096 chunks
            int n = idx >> 4, ch = idx & 15;
            uint32_t off = n * 256 + ((ch ^ (n & 7)) << 4);
            cp16(sb + SM_BHI + off, Bg0 + n * 128 + ch * 8, 16);
        }
        idx = tid;
        #pragma unroll
        for (int j = 0; j < 4; ++j, idx += GT) {  // BLO: 2048 chunks
            int n = idx >> 4, ch = idx & 15;
            uint32_t off = n * 256 + ((ch ^ (n & 7)) << 4);
            cp16(sb + SM_BLO + off, Bg1 + n * 128 + ch * 8, 16);
        }
    }
    // ---- first A tile, same group as B
    int t = blockIdx.x;
    const int stride = gridDim.x;
    if (t < ntiles) prefetch_A(sb, 0, feath, row_base + t * 128, nrows);
    cp_commit();

    const int wid = tid >> 5, lane = tid & 31;
    const int mw = wid & 3;
    const int nw = wid >> 2;
    const bool self_half = (nw < 2);
    const int s3 = lane & 7, sel = lane >> 3;
    const int g = lane >> 2, tq = lane & 3;
    const int colhalf = (nw & 1) * 64;

    int cur = 0;
    bool first = true;
    for (; t < ntiles; t += stride, cur ^= 1) {
        const int row0 = row_base + t * 128;
        const int nt_tile = t + stride;
        const bool has_next = (nt_tile < ntiles);

        if (has_next) {
            prefetch_A(sb, cur ^ 1, feath, row_base + nt_tile * 128, nrows);
            cp_commit();
            asm volatile("cp.async.wait_group 1;" ::: "memory");
        } else {
            asm volatile("cp.async.wait_group 0;" ::: "memory");
        }
        __syncthreads();                      // A(cur) visible; prev reads done
        (void)first; first = false;

        const uint32_t abase = sb + (cur ? SM_A1 : SM_A0);

        float acc[2][8][4];
        #pragma unroll
        for (int a = 0; a < 2; ++a)
            #pragma unroll
            for (int b = 0; b < 8; ++b)
                #pragma unroll
                for (int c = 0; c < 4; ++c) acc[a][b][c] = 0.f;

        #pragma unroll
        for (int ks = 0; ks < 8; ++ks) {
            uint32_t ahi[2][4];
            #pragma unroll
            for (int mt = 0; mt < 2; ++mt) {
                int r = mw * 32 + mt * 16 + s3 + ((sel & 1) << 3);
                int ch = 2 * ks + (sel >> 1);
                uint32_t off = r * 256 + ((ch ^ (r & 7)) << 4);
                ldsm_x4(ahi[mt], abase + off);
            }
            #pragma unroll
            for (int jp = 0; jp < 4; ++jp) {
                int r = nw * 64 + jp * 16 + s3 + ((sel >> 1) << 3);
                int ch = 2 * ks + (sel & 1);
                uint32_t off = r * 256 + ((ch ^ (r & 7)) << 4);
                uint32_t bhi[4], blo[4];
                ldsm_x4(bhi, sb + SM_BHI + off);
                if (self_half) ldsm_x4(blo, sb + SM_BLO + off);
                #pragma unroll
                for (int tt = 0; tt < 2; ++tt) {
                    int nt = jp * 2 + tt;
                    #pragma unroll
                    for (int mt = 0; mt < 2; ++mt) {
                        mma16816(acc[mt][nt], ahi[mt], bhi[2*tt], bhi[2*tt+1]);
                        if (self_half)
                            mma16816(acc[mt][nt], ahi[mt], blo[2*tt], blo[2*tt+1]);
                    }
                }
            }
        }

        // ---- epilogue (global only)
        #pragma unroll
        for (int mt = 0; mt < 2; ++mt) {
            int rr = row0 + mw * 32 + mt * 16 + g;
            #pragma unroll
            for (int nt = 0; nt < 8; ++nt) {
                int col = colhalf + nt * 8 + 2 * tq;
                if (self_half) {
                    if (rr < nrows)
                        *(float2*)(out_self + (size_t)rr * 128 + col) =
                            make_float2(acc[mt][nt][0], acc[mt][nt][1]);
                    if (rr + 8 < nrows)
                        *(float2*)(out_self + (size_t)(rr + 8) * 128 + col) =
                            make_float2(acc[mt][nt][2], acc[mt][nt][3]);
                } else {
                    if (rr < nrows)
                        *(__half2*)(out_msg + (size_t)rr * 128 + col) =
                            __floats2half2_rn(acc[mt][nt][0], acc[mt][nt][1]);
                    if (rr + 8 < nrows)
                        *(__half2*)(out_msg + (size_t)(rr + 8) * 128 + col) =
                            __floats2half2_rn(acc[mt][nt][2], acc[mt][nt][3]);
                }
            }
        }
        __syncthreads();                      // buf free for next prefetch
    }
}

// ------- CSR gather-mean (fp16 msg) + combine (+ReLU); fp32 or fp16 output ------
__global__ void agg_csr_kernel(const __half* __restrict__ msg,
                               const float* __restrict__ self,
                               float* __restrict__ outf,
                               __half* __restrict__ outh,
                               int node_base, int node_end, int relu)
{
    int w = node_base + ((blockIdx.x * blockDim.x + threadIdx.x) >> 5);
    if (w >= node_end) return;
    int lane = threadIdx.x & 31;

    int beg = __ldg(&g_row_start[w]);
    int end = __ldg(&g_row_start[w + 1]);

    float4 a0 = make_float4(0.f, 0.f, 0.f, 0.f);
    float4 a1 = make_float4(0.f, 0.f, 0.f, 0.f);
    float4 a2 = make_float4(0.f, 0.f, 0.f, 0.f);
    float4 a3 = make_float4(0.f, 0.f, 0.f, 0.f);

    int e = beg;
    for (; e + 8 <= end; e += 8) {
        int s[8];
        #pragma unroll
        for (int j = 0; j < 8; ++j) s[j] = __ldg(&g_csr[e + j]);
        uint2 u[8];
        #pragma unroll
        for (int j = 0; j < 8; ++j)
            u[j] = __ldg((const uint2*)(msg + (size_t)s[j] * 128) + lane);
        #pragma unroll
        for (int j = 0; j < 8; ++j) {
            float2 f0 = __half22float2(*(__half2*)&u[j].x);
            float2 f1 = __half22float2(*(__half2*)&u[j].y);
            float4* a = (j & 2) ? ((j & 1) ? &a3 : &a2) : ((j & 1) ? &a1 : &a0);
            a->x += f0.x; a->y += f0.y; a->z += f1.x; a->w += f1.y;
        }
    }
    for (; e + 2 <= end; e += 2) {
        int s0 = __ldg(&g_csr[e]), s1 = __ldg(&g_csr[e + 1]);
        uint2 u0 = __ldg((const uint2*)(msg + (size_t)s0 * 128) + lane);
        uint2 u1 = __ldg((const uint2*)(msg + (size_t)s1 * 128) + lane);
        float2 f;
        f = __half22float2(*(__half2*)&u0.x); a0.x += f.x; a0.y += f.y;
        f = __half22float2(*(__half2*)&u0.y); a0.z += f.x; a0.w += f.y;
        f = __half22float2(*(__half2*)&u1.x); a1.x += f.x; a1.y += f.y;
        f = __half22float2(*(__half2*)&u1.y); a1.z += f.x; a1.w += f.y;
    }
    if (e < end) {
        int s0 = __ldg(&g_csr[e]);
        uint2 u0 = __ldg((const uint2*)(msg + (size_t)s0 * 128) + lane);
        float2 f;
        f = __half22float2(*(__half2*)&u0.x); a0.x += f.x; a0.y += f.y;
        f = __half22float2(*(__half2*)&u0.y); a0.z += f.x; a0.w += f.y;
    }

    a0.x += a1.x; a0.y += a1.y; a0.z += a1.z; a0.w += a1.w;
    a2.x += a3.x; a2.y += a3.y; a2.z += a3.z; a2.w += a3.w;
    a0.x += a2.x; a0.y += a2.y; a0.z += a2.z; a0.w += a2.w;

    float inv = 1.0f / fmaxf((float)(end - beg), 1.0f);
    float4 sf = ((const float4*)self)[w * 32 + lane];
    float4 o;
    o.x = fmaf(a0.x, inv, sf.x);
    o.y = fmaf(a0.y, inv, sf.y);
    o.z = fmaf(a0.z, inv, sf.z);
    o.w = fmaf(a0.w, inv, sf.w);
    if (relu) {
        o.x = fmaxf(o.x, 0.f); o.y = fmaxf(o.y, 0.f);
        o.z = fmaxf(o.z, 0.f); o.w = fmaxf(o.w, 0.f);
    }
    if (outf) {
        ((float4*)outf)[w * 32 + lane] = o;
    } else {
        uint2 p;
        __half2 t;
        t = __floats2half2_rn(o.x, o.y); p.x = *(uint32_t*)&t;
        t = __floats2half2_rn(o.z, o.w); p.y = *(uint32_t*)&t;
        ((uint2*)outh)[w * 32 + lane] = p;
    }
}

// --------------------------------------------------------------------------------
extern "C" void kernel_launch(void* const* d_in, const int* in_sizes, int n_in,
                              void* d_out, int out_size)
{
    const float* x     = (const float*)d_in[0];
    const float* W_in  = (const float*)d_in[1];
    const float* W_out = (const float*)d_in[2];
    const int*   src   = (const int*)d_in[3];
    const int*   dst   = (const int*)d_in[4];
    float*       out   = (float*)d_out;

    const int N = in_sizes[0] / FEAT;
    const int E = in_sizes[3];
    const int Nh = ((N / 2 + 127) / 128) * 128;

    float *p_self, *p_self2;
    __half *p_msg, *p_msg2, *p_hh, *p_xh;
    int *p_deg;
    __half *p_B0, *p_B1;
    cudaGetSymbolAddress((void**)&p_self,  g_self);
    cudaGetSymbolAddress((void**)&p_self2, g_self2);
    cudaGetSymbolAddress((void**)&p_msg,   g_msg);
    cudaGetSymbolAddress((void**)&p_msg2,  g_msg2);
    cudaGetSymbolAddress((void**)&p_hh,    g_hh);
    cudaGetSymbolAddress((void**)&p_xh,    g_xh);
    cudaGetSymbolAddress((void**)&p_deg,   g_deg);
    cudaGetSymbolAddress((void**)&p_B0,    g_B0);
    cudaGetSymbolAddress((void**)&p_B1,    g_B1);

    static bool s_init = false;
    static cudaStream_t s2 = 0;
    static cudaEvent_t evF = 0, evJ = 0, evA0 = 0, evG0 = 0;
    static int n_sm = 148;
    if (!s_init) {
        cudaFuncSetAttribute(mma_gemm_kernel,
                             cudaFuncAttributeMaxDynamicSharedMemorySize,
                             SMEM_TOTAL_GEMM);
        if (cudaStreamCreateWithFlags(&s2, cudaStreamNonBlocking) != cudaSuccess)
            s2 = 0;
        cudaEventCreateWithFlags(&evF,  cudaEventDisableTiming);
        cudaEventCreateWithFlags(&evJ,  cudaEventDisableTiming);
        cudaEventCreateWithFlags(&evA0, cudaEventDisableTiming);
        cudaEventCreateWithFlags(&evG0, cudaEventDisableTiming);
        cudaDeviceGetAttribute(&n_sm, cudaDevAttrMultiProcessorCount, 0);
        s_init = true;
    }

    const int egrid = (E + 255) / 256;
    const __half* B0L2 = p_B0 + 256 * 128;
    const __half* B1L2 = p_B1 + 256 * 128;

    auto agg_grid = [](int nodes) { return (nodes * 32 + 127) / 128; };
    auto tiles = [](int rows) { return (rows + 127) / 128; };
    auto pgrid = [&](int nt) { return nt < n_sm ? nt : n_sm; };

    // ---- fork: CSR build on s2; default: wprep -> xh -> gemm1 (launch #4) ----
    cudaEventRecord(evF, 0);
    cudaStreamWaitEvent(s2, evF, 0);
    zero_int_kernel<<<(N + 255) / 256, 256, 0, s2>>>(p_deg, N);          // #1
    wprep_kernel<<<(2 * 256 * 128 + 255) / 256, 256>>>(W_in, W_out);     // #2
    xh_kernel<<<(N * 32 + 255) / 256, 256>>>(x, N * 32);                 // #3
    {
        int nt = tiles(N);
        mma_gemm_kernel<<<pgrid(nt), GT, SMEM_TOTAL_GEMM>>>(             // #4
            p_xh, p_B0, p_B1, p_self, p_msg, 0, N, nt);
    }
    deg_kernel<<<egrid, 256, 0, s2>>>(dst, E);
    scan_kernel<<<1, 1024, 0, s2>>>(N);
    fill_kernel<<<egrid, 256, 0, s2>>>(src, dst, E);
    cudaEventRecord(evJ, s2);

    // ---- layer 1 aggregation, chunked; h stored fp16 ----
    cudaStreamWaitEvent(0, evJ, 0);
    agg_csr_kernel<<<agg_grid(Nh), 128>>>(p_msg, p_self, nullptr, p_hh, 0, Nh, 1);
    cudaEventRecord(evA0, 0);

    // gemm2 chunk0 on s2, concurrent with agg1 chunk1 on default
    cudaStreamWaitEvent(s2, evA0, 0);
    {
        int nt = tiles(Nh);
        mma_gemm_kernel<<<pgrid(nt), GT, SMEM_TOTAL_GEMM, s2>>>(
            p_hh, B0L2, B1L2, p_self2, p_msg2, 0, N, nt);
    }
    cudaEventRecord(evG0, s2);

    agg_csr_kernel<<<agg_grid(N - Nh), 128>>>(p_msg, p_self, nullptr, p_hh, Nh, N, 1);
    {
        int nt = tiles(N - Nh);
        mma_gemm_kernel<<<pgrid(nt), GT, SMEM_TOTAL_GEMM>>>(
            p_hh, B0L2, B1L2, p_self2, p_msg2, Nh, N, nt);
    }

    // ---- layer 2 aggregation ----
    cudaStreamWaitEvent(0, evG0, 0);
    agg_csr_kernel<<<agg_grid(N), 128>>>(p_msg2, p_self2, out, nullptr, 0, N, 0);
}

// round 11
// speedup vs baseline: 1.2746x; 1.0071x over previous
#include <cuda_runtime.h>
#include <cuda_bf16.h>
#include <cuda_fp16.h>
#include <cstdint>

#define NNODES 100000
#define NEDGES 1600000
#define FEAT   128

// -------- scratch (static device globals; allocation-free per harness rules) ----
__device__ __align__(16) float  g_self [NNODES * FEAT];  // layer1 self (fp32)
__device__ __align__(16) __half g_msg  [NNODES * FEAT];  // layer1 msg  (fp16)
__device__ __align__(16) __half g_hh   [NNODES * FEAT];  // hidden h    (fp16)
__device__ __align__(16) float  g_self2[NNODES * FEAT];  // layer2 self (fp32)
__device__ __align__(16) __half g_msg2 [NNODES * FEAT];  // layer2 msg  (fp16)
__device__ __align__(16) __half g_xh   [NNODES * FEAT];  // x rounded to fp16
__device__ int g_deg[NNODES];
__device__ int g_row_start[NNODES + 1];
__device__ int g_csr[NEDGES];
// fp16 split weights, pre-transposed to [layer][n(0..255)][k(0..127)]
__device__ __align__(16) __half g_B0[2 * 256 * 128];   // hi
__device__ __align__(16) __half g_B1[2 * 256 * 128];   // lo (residual)

// ================================ helpers =======================================
__device__ __forceinline__ uint32_t sm_u32(const void* p) {
    uint32_t a;
    asm("{ .reg .u64 t; cvta.to.shared.u64 t, %1; cvt.u32.u64 %0, t; }"
        : "=r"(a) : "l"(p));
    return a;
}
__device__ __forceinline__ void ldsm_x4(uint32_t* r, uint32_t addr) {
    asm volatile("ldmatrix.sync.aligned.m8n8.x4.shared.b16 {%0,%1,%2,%3}, [%4];"
                 : "=r"(r[0]), "=r"(r[1]), "=r"(r[2]), "=r"(r[3]) : "r"(addr));
}
__device__ __forceinline__ void mma16816(float* c, const uint32_t* a,
                                         uint32_t b0, uint32_t b1) {
    asm volatile("mma.sync.aligned.m16n8k16.row.col.f32.f16.f16.f32 "
                 "{%0,%1,%2,%3}, {%4,%5,%6,%7}, {%8,%9}, {%0,%1,%2,%3};"
                 : "+f"(c[0]), "+f"(c[1]), "+f"(c[2]), "+f"(c[3])
                 : "r"(a[0]), "r"(a[1]), "r"(a[2]), "r"(a[3]), "r"(b0), "r"(b1));
}
__device__ __forceinline__ void cp16(uint32_t saddr, const void* g, int src_sz) {
    asm volatile("cp.async.cg.shared.global [%0], [%1], 16, %2;"
                 :: "r"(saddr), "l"(g), "r"(src_sz) : "memory");
}
__device__ __forceinline__ void cp_commit() {
    asm volatile("cp.async.commit_group;" ::: "memory");
}
// ---- L2 eviction-priority via createpolicy + cache_hint (any access width) ----
__device__ __forceinline__ uint64_t pol_evict_last() {
    uint64_t p;
    asm("createpolicy.fractional.L2::evict_last.b64 %0, 1.0;" : "=l"(p));
    return p;
}
__device__ __forceinline__ uint64_t pol_evict_first() {
    uint64_t p;
    asm("createpolicy.fractional.L2::evict_first.b64 %0, 1.0;" : "=l"(p));
    return p;
}
__device__ __forceinline__ uint2 ldg_hint_u2(const void* p, uint64_t pol) {
    uint2 v;
    asm volatile("ld.global.nc.L2::cache_hint.v2.u32 {%0,%1}, [%2], %3;"
                 : "=r"(v.x), "=r"(v.y) : "l"(p), "l"(pol));
    return v;
}
__device__ __forceinline__ float4 ldg_hint_f4(const void* p, uint64_t pol) {
    float4 v;
    asm volatile("ld.global.nc.L2::cache_hint.v4.f32 {%0,%1,%2,%3}, [%4], %5;"
                 : "=f"(v.x), "=f"(v.y), "=f"(v.z), "=f"(v.w) : "l"(p), "l"(pol));
    return v;
}
__device__ __forceinline__ void stg_hint_f4(void* p, float4 v, uint64_t pol) {
    asm volatile("st.global.L2::cache_hint.v4.f32 [%0], {%1,%2,%3,%4}, %5;"
                 :: "l"(p), "f"(v.x), "f"(v.y), "f"(v.z), "f"(v.w), "l"(pol)
                 : "memory");
}
__device__ __forceinline__ void stg_hint_f2(void* p, float2 v, uint64_t pol) {
    asm volatile("st.global.L2::cache_hint.v2.f32 [%0], {%1,%2}, %3;"
                 :: "l"(p), "f"(v.x), "f"(v.y), "l"(pol) : "memory");
}
__device__ __forceinline__ void stg_hint_u32(void* p, uint32_t v, uint64_t pol) {
    asm volatile("st.global.L2::cache_hint.u32 [%0], %1, %2;"
                 :: "l"(p), "r"(v), "l"(pol) : "memory");
}

// ============================= prep kernels (once) ==============================
__global__ void wprep_kernel(const float* __restrict__ W_in,
                             const float* __restrict__ W_out) {
    int idx = blockIdx.x * blockDim.x + threadIdx.x;
    if (idx >= 2 * 256 * 128) return;
    int layer = idx >> 15;
    int n = (idx >> 7) & 255;
    int k = idx & 127;
    const float* W = (layer ? W_out : W_in) + ((n >= 128) ? 128 * 128 : 0);
    float w = W[k * 128 + (n & 127)];
    __half w0 = __float2half_rn(w);
    __half w1 = __float2half_rn(w - __half2float(w0));
    g_B0[idx] = w0;
    g_B1[idx] = w1;
}
__global__ void xh_kernel(const float* __restrict__ x, int n4) {
    int i = blockIdx.x * blockDim.x + threadIdx.x;
    if (i >= n4) return;
    float4 v = ((const float4*)x)[i];
    __half2 t0 = __floats2half2_rn(v.x, v.y);
    __half2 t1 = __floats2half2_rn(v.z, v.w);
    uint2 p = make_uint2(*(uint32_t*)&t0, *(uint32_t*)&t1);
    ((uint2*)g_xh)[i] = p;
}

// =============================== CSR build ======================================
__global__ void zero_int_kernel(int* __restrict__ a, int n) {
    int i = blockIdx.x * blockDim.x + threadIdx.x;
    if (i < n) a[i] = 0;
}
__global__ void deg_kernel(const int* __restrict__ dst, int E) {
    int e = blockIdx.x * blockDim.x + threadIdx.x;
    if (e < E) atomicAdd(&g_deg[dst[e]], 1);
}
__global__ void scan_kernel(int n) {
    __shared__ int part[1024];
    const int T = 1024;
    int tid = threadIdx.x;
    int chunk = (n + T - 1) / T;
    int b = tid * chunk, e = min(b + chunk, n);
    int s = 0;
    for (int i = b; i < e; ++i) s += g_deg[i];
    part[tid] = s;
    __syncthreads();
    if (tid == 0) {
        int run = 0;
        for (int i = 0; i < T; ++i) { int t = part[i]; part[i] = run; run += t; }
    }
    __syncthreads();
    int run = part[tid];
    for (int i = b; i < e; ++i) { g_row_start[i] = run; run += g_deg[i]; }
    if (e == n) g_row_start[n] = run;
}
__global__ void fill_kernel(const int* __restrict__ src,
                            const int* __restrict__ dst, int E) {
    int e = blockIdx.x * blockDim.x + threadIdx.x;
    if (e < E) {
        int d = dst[e];
        int slot = g_row_start[d] + atomicSub(&g_deg[d], 1) - 1;
        g_csr[slot] = src[e];
    }
}

// ====== persistent mma.sync dual GEMM, cp.async double-buffered A ===============
#define GT 512
#define SM_A0  0                 // 32 KB
#define SM_A1  32768             // 32 KB
#define SM_BHI 65536             // 64 KB (256 rows)
#define SM_BLO 131072            // 32 KB (self half only)
#define SMEM_TOTAL_GEMM 163840

__device__ __forceinline__ void prefetch_A(uint32_t sb, int buf,
                                           const __half* __restrict__ feath,
                                           int row0, int nrows) {
    const uint32_t base = sb + (buf ? SM_A1 : SM_A0);
    int idx = threadIdx.x;
    #pragma unroll
    for (int j = 0; j < 4; ++j, idx += GT) {
        int r = idx >> 4, ch = idx & 15;
        int row = row0 + r;
        uint32_t off = r * 256 + ((ch ^ (r & 7)) << 4);
        cp16(base + off, feath + (size_t)row * 128 + ch * 8,
             (row < nrows) ? 16 : 0);
    }
}

__global__ __launch_bounds__(GT, 1)
void mma_gemm_kernel(const __half* __restrict__ feath,
                     const __half* __restrict__ Bg0,
                     const __half* __restrict__ Bg1,
                     float* __restrict__ out_self,
                     __half* __restrict__ out_msg,
                     int row_base, int nrows, int ntiles)
{
    extern __shared__ char smc[];
    const int tid = threadIdx.x;
    const uint32_t sb = sm_u32(smc);

    {
        int idx = tid;
        #pragma unroll
        for (int j = 0; j < 8; ++j, idx += GT) {
            int n = idx >> 4, ch = idx & 15;
            uint32_t off = n * 256 + ((ch ^ (n & 7)) << 4);
            cp16(sb + SM_BHI + off, Bg0 + n * 128 + ch * 8, 16);
        }
        idx = tid;
        #pragma unroll
        for (int j = 0; j < 4; ++j, idx += GT) {
            int n = idx >> 4, ch = idx & 15;
            uint32_t off = n * 256 + ((ch ^ (n & 7)) << 4);
            cp16(sb + SM_BLO + off, Bg1 + n * 128 + ch * 8, 16);
        }
    }
    int t = blockIdx.x;
    const int stride = gridDim.x;
    if (t < ntiles) prefetch_A(sb, 0, feath, row_base + t * 128, nrows);
    cp_commit();

    const int wid = tid >> 5, lane = tid & 31;
    const int mw = wid & 3;
    const int nw = wid >> 2;
    const bool self_half = (nw < 2);
    const int s3 = lane & 7, sel = lane >> 3;
    const int g = lane >> 2, tq = lane & 3;
    const int colhalf = (nw & 1) * 64;
    const uint64_t pL = pol_evict_last();
    const uint64_t pF = pol_evict_first();

    int cur = 0;
    for (; t < ntiles; t += stride, cur ^= 1) {
        const int row0 = row_base + t * 128;
        const int nt_tile = t + stride;
        const bool has_next = (nt_tile < ntiles);

        if (has_next) {
            prefetch_A(sb, cur ^ 1, feath, row_base + nt_tile * 128, nrows);
            cp_commit();
            asm volatile("cp.async.wait_group 1;" ::: "memory");
        } else {
            asm volatile("cp.async.wait_group 0;" ::: "memory");
        }
        __syncthreads();

        const uint32_t abase = sb + (cur ? SM_A1 : SM_A0);

        float acc[2][8][4];
        #pragma unroll
        for (int a = 0; a < 2; ++a)
            #pragma unroll
            for (int b = 0; b < 8; ++b)
                #pragma unroll
                for (int c = 0; c < 4; ++c) acc[a][b][c] = 0.f;

        #pragma unroll
        for (int ks = 0; ks < 8; ++ks) {
            uint32_t ahi[2][4];
            #pragma unroll
            for (int mt = 0; mt < 2; ++mt) {
                int r = mw * 32 + mt * 16 + s3 + ((sel & 1) << 3);
                int ch = 2 * ks + (sel >> 1);
                uint32_t off = r * 256 + ((ch ^ (r & 7)) << 4);
                ldsm_x4(ahi[mt], abase + off);
            }
            #pragma unroll
            for (int jp = 0; jp < 4; ++jp) {
                int r = nw * 64 + jp * 16 + s3 + ((sel >> 1) << 3);
                int ch = 2 * ks + (sel & 1);
                uint32_t off = r * 256 + ((ch ^ (r & 7)) << 4);
                uint32_t bhi[4], blo[4];
                ldsm_x4(bhi, sb + SM_BHI + off);
                if (self_half) ldsm_x4(blo, sb + SM_BLO + off);
                #pragma unroll
                for (int tt = 0; tt < 2; ++tt) {
                    int nt = jp * 2 + tt;
                    #pragma unroll
                    for (int mt = 0; mt < 2; ++mt) {
                        mma16816(acc[mt][nt], ahi[mt], bhi[2*tt], bhi[2*tt+1]);
                        if (self_half)
                            mma16816(acc[mt][nt], ahi[mt], blo[2*tt], blo[2*tt+1]);
                    }
                }
            }
        }

        // ---- epilogue: self -> evict_first stream; msg -> evict_last (reuse set)
        #pragma unroll
        for (int mt = 0; mt < 2; ++mt) {
            int rr = row0 + mw * 32 + mt * 16 + g;
            #pragma unroll
            for (int nt = 0; nt < 8; ++nt) {
                int col = colhalf + nt * 8 + 2 * tq;
                if (self_half) {
                    if (rr < nrows)
                        stg_hint_f2(out_self + (size_t)rr * 128 + col,
                                    make_float2(acc[mt][nt][0], acc[mt][nt][1]), pF);
                    if (rr + 8 < nrows)
                        stg_hint_f2(out_self + (size_t)(rr + 8) * 128 + col,
                                    make_float2(acc[mt][nt][2], acc[mt][nt][3]), pF);
                } else {
                    if (rr < nrows) {
                        __half2 h = __floats2half2_rn(acc[mt][nt][0], acc[mt][nt][1]);
                        stg_hint_u32(out_msg + (size_t)rr * 128 + col,
                                     *(uint32_t*)&h, pL);
                    }
                    if (rr + 8 < nrows) {
                        __half2 h = __floats2half2_rn(acc[mt][nt][2], acc[mt][nt][3]);
                        stg_hint_u32(out_msg + (size_t)(rr + 8) * 128 + col,
                                     *(uint32_t*)&h, pL);
                    }
                }
            }
        }
        __syncthreads();
    }
}

// ------- CSR gather-mean (fp16 msg, L2-pinned) + combine (+ReLU) ----------------
__global__ void agg_csr_kernel(const __half* __restrict__ msg,
                               const float* __restrict__ self,
                               float* __restrict__ outf,
                               __half* __restrict__ outh,
                               int node_base, int node_end, int relu)
{
    int w = node_base + ((blockIdx.x * blockDim.x + threadIdx.x) >> 5);
    if (w >= node_end) return;
    int lane = threadIdx.x & 31;
    const uint64_t pL = pol_evict_last();
    const uint64_t pF = pol_evict_first();

    int beg = __ldg(&g_row_start[w]);
    int end = __ldg(&g_row_start[w + 1]);

    float4 a0 = make_float4(0.f, 0.f, 0.f, 0.f);
    float4 a1 = make_float4(0.f, 0.f, 0.f, 0.f);
    float4 a2 = make_float4(0.f, 0.f, 0.f, 0.f);
    float4 a3 = make_float4(0.f, 0.f, 0.f, 0.f);

    int e = beg;
    for (; e + 8 <= end; e += 8) {
        int s[8];
        #pragma unroll
        for (int j = 0; j < 8; ++j) s[j] = __ldg(&g_csr[e + j]);
        uint2 u[8];
        #pragma unroll
        for (int j = 0; j < 8; ++j)
            u[j] = ldg_hint_u2((const uint2*)(msg + (size_t)s[j] * 128) + lane, pL);
        #pragma unroll
        for (int j = 0; j < 8; ++j) {
            float2 f0 = __half22float2(*(__half2*)&u[j].x);
            float2 f1 = __half22float2(*(__half2*)&u[j].y);
            float4* a = (j & 2) ? ((j & 1) ? &a3 : &a2) : ((j & 1) ? &a1 : &a0);
            a->x += f0.x; a->y += f0.y; a->z += f1.x; a->w += f1.y;
        }
    }
    for (; e + 2 <= end; e += 2) {
        int s0 = __ldg(&g_csr[e]), s1 = __ldg(&g_csr[e + 1]);
        uint2 u0 = ldg_hint_u2((const uint2*)(msg + (size_t)s0 * 128) + lane, pL);
        uint2 u1 = ldg_hint_u2((const uint2*)(msg + (size_t)s1 * 128) + lane, pL);
        float2 f;
        f = __half22float2(*(__half2*)&u0.x); a0.x += f.x; a0.y += f.y;
        f = __half22float2(*(__half2*)&u0.y); a0.z += f.x; a0.w += f.y;
        f = __half22float2(*(__half2*)&u1.x); a1.x += f.x; a1.y += f.y;
        f = __half22float2(*(__half2*)&u1.y); a1.z += f.x; a1.w += f.y;
    }
    if (e < end) {
        int s0 = __ldg(&g_csr[e]);
        uint2 u0 = ldg_hint_u2((const uint2*)(msg + (size_t)s0 * 128) + lane, pL);
        float2 f;
        f = __half22float2(*(__half2*)&u0.x); a0.x += f.x; a0.y += f.y;
        f = __half22float2(*(__half2*)&u0.y); a0.z += f.x; a0.w += f.y;
    }

    a0.x += a1.x; a0.y += a1.y; a0.z += a1.z; a0.w += a1.w;
    a2.x += a3.x; a2.y += a3.y; a2.z += a3.z; a2.w += a3.w;
    a0.x += a2.x; a0.y += a2.y; a0.z += a2.z; a0.w += a2.w;

    float inv = 1.0f / fmaxf((float)(end - beg), 1.0f);
    float4 sf = ldg_hint_f4((const float4*)self + w * 32 + lane, pF);
    float4 o;
    o.x = fmaf(a0.x, inv, sf.x);
    o.y = fmaf(a0.y, inv, sf.y);
    o.z = fmaf(a0.z, inv, sf.z);
    o.w = fmaf(a0.w, inv, sf.w);
    if (relu) {
        o.x = fmaxf(o.x, 0.f); o.y = fmaxf(o.y, 0.f);
        o.z = fmaxf(o.z, 0.f); o.w = fmaxf(o.w, 0.f);
    }
    if (outf) {
        stg_hint_f4((float4*)outf + w * 32 + lane, o, pF);
    } else {
        uint2 p;
        __half2 t;
        t = __floats2half2_rn(o.x, o.y); p.x = *(uint32_t*)&t;
        t = __floats2half2_rn(o.z, o.w); p.y = *(uint32_t*)&t;
        ((uint2*)outh)[w * 32 + lane] = p;   // h: re-read soon, evict_normal
    }
}

// --------------------------------------------------------------------------------
extern "C" void kernel_launch(void* const* d_in, const int* in_sizes, int n_in,
                              void* d_out, int out_size)
{
    const float* x     = (const float*)d_in[0];
    const float* W_in  = (const float*)d_in[1];
    const float* W_out = (const float*)d_in[2];
    const int*   src   = (const int*)d_in[3];
    const int*   dst   = (const int*)d_in[4];
    float*       out   = (float*)d_out;

    const int N = in_sizes[0] / FEAT;
    const int E = in_sizes[3];
    const int Nh = ((N / 2 + 127) / 128) * 128;

    float *p_self, *p_self2;
    __half *p_msg, *p_msg2, *p_hh, *p_xh;
    int *p_deg;
    __half *p_B0, *p_B1;
    cudaGetSymbolAddress((void**)&p_self,  g_self);
    cudaGetSymbolAddress((void**)&p_self2, g_self2);
    cudaGetSymbolAddress((void**)&p_msg,   g_msg);
    cudaGetSymbolAddress((void**)&p_msg2,  g_msg2);
    cudaGetSymbolAddress((void**)&p_hh,    g_hh);
    cudaGetSymbolAddress((void**)&p_xh,    g_xh);
    cudaGetSymbolAddress((void**)&p_deg,   g_deg);
    cudaGetSymbolAddress((void**)&p_B0,    g_B0);
    cudaGetSymbolAddress((void**)&p_B1,    g_B1);

    static bool s_init = false;
    static cudaStream_t s2 = 0;
    static cudaEvent_t evF = 0, evJ = 0, evA0 = 0, evG0 = 0;
    static int n_sm = 148;
    if (!s_init) {
        cudaFuncSetAttribute(mma_gemm_kernel,
                             cudaFuncAttributeMaxDynamicSharedMemorySize,
                             SMEM_TOTAL_GEMM);
        if (cudaStreamCreateWithFlags(&s2, cudaStreamNonBlocking) != cudaSuccess)
            s2 = 0;
        cudaEventCreateWithFlags(&evF,  cudaEventDisableTiming);
        cudaEventCreateWithFlags(&evJ,  cudaEventDisableTiming);
        cudaEventCreateWithFlags(&evA0, cudaEventDisableTiming);
        cudaEventCreateWithFlags(&evG0, cudaEventDisableTiming);
        cudaDeviceGetAttribute(&n_sm, cudaDevAttrMultiProcessorCount, 0);
        s_init = true;
    }

    const int egrid = (E + 255) / 256;
    const __half* B0L2 = p_B0 + 256 * 128;
    const __half* B1L2 = p_B1 + 256 * 128;

    auto agg_grid = [](int nodes) { return (nodes * 32 + 127) / 128; };
    auto tiles = [](int rows) { return (rows + 127) / 128; };
    auto pgrid = [&](int nt) { return nt < n_sm ? nt : n_sm; };

    // ---- fork: CSR build on s2; default: wprep -> xh -> gemm1 (launch #4) ----
    cudaEventRecord(evF, 0);
    cudaStreamWaitEvent(s2, evF, 0);
    zero_int_kernel<<<(N + 255) / 256, 256, 0, s2>>>(p_deg, N);          // #1
    wprep_kernel<<<(2 * 256 * 128 + 255) / 256, 256>>>(W_in, W_out);     // #2
    xh_kernel<<<(N * 32 + 255) / 256, 256>>>(x, N * 32);                 // #3
    {
        int nt = tiles(N);
        mma_gemm_kernel<<<pgrid(nt), GT, SMEM_TOTAL_GEMM>>>(             // #4
            p_xh, p_B0, p_B1, p_self, p_msg, 0, N, nt);
    }
    deg_kernel<<<egrid, 256, 0, s2>>>(dst, E);
    scan_kernel<<<1, 1024, 0, s2>>>(N);
    fill_kernel<<<egrid, 256, 0, s2>>>(src, dst, E);
    cudaEventRecord(evJ, s2);

    // ---- layer 1 aggregation, chunked; h stored fp16 ----
    cudaStreamWaitEvent(0, evJ, 0);
    agg_csr_kernel<<<agg_grid(Nh), 128>>>(p_msg, p_self, nullptr, p_hh, 0, Nh, 1);
    cudaEventRecord(evA0, 0);

    // gemm2 chunk0 on s2, concurrent with agg1 chunk1 on default
    cudaStreamWaitEvent(s2, evA0, 0);
    {
        int nt = tiles(Nh);
        mma_gemm_kernel<<<pgrid(nt), GT, SMEM_TOTAL_GEMM, s2>>>(
            p_hh, B0L2, B1L2, p_self2, p_msg2, 0, N, nt);
    }
    cudaEventRecord(evG0, s2);

    agg_csr_kernel<<<agg_grid(N - Nh), 128>>>(p_msg, p_self, nullptr, p_hh, Nh, N, 1);
    {
        int nt = tiles(N - Nh);
        mma_gemm_kernel<<<pgrid(nt), GT, SMEM_TOTAL_GEMM>>>(
            p_hh, B0L2, B1L2, p_self2, p_msg2, Nh, N, nt);
    }

    // ---- layer 2 aggregation ----
    cudaStreamWaitEvent(0, evG0, 0);
    agg_csr_kernel<<<agg_grid(N), 128>>>(p_msg2, p_self2, out, nullptr, 0, N, 0);
}

// round 12
// speedup vs baseline: 1.3267x; 1.0409x over previous
#include <cuda_runtime.h>
#include <cuda_bf16.h>
#include <cuda_fp16.h>
#include <cstdint>

#define NNODES 100000
#define NEDGES 1600000
#define FEAT   128

// -------- scratch (static device globals; allocation-free per harness rules) ----
__device__ __align__(16) float  g_self [NNODES * FEAT];  // layer1 self (fp32)
__device__ __align__(16) __half g_msg  [NNODES * FEAT];  // layer1 msg  (fp16)
__device__ __align__(16) __half g_hh   [NNODES * FEAT];  // hidden h    (fp16)
__device__ __align__(16) float  g_self2[NNODES * FEAT];  // layer2 self (fp32)
__device__ __align__(16) __half g_msg2 [NNODES * FEAT];  // layer2 msg  (fp16)
__device__ __align__(16) __half g_xh   [NNODES * FEAT];  // x rounded to fp16
__device__ int g_deg[NNODES];
__device__ int g_row_start[NNODES + 1];
__device__ int g_csr[NEDGES];
// fp16 split weights, pre-transposed to [layer][n(0..255)][k(0..127)]
__device__ __align__(16) __half g_B0[2 * 256 * 128];   // hi
__device__ __align__(16) __half g_B1[2 * 256 * 128];   // lo (residual)

// ================================ helpers =======================================
__device__ __forceinline__ uint32_t sm_u32(const void* p) {
    uint32_t a;
    asm("{ .reg .u64 t; cvta.to.shared.u64 t, %1; cvt.u32.u64 %0, t; }"
        : "=r"(a) : "l"(p));
    return a;
}
__device__ __forceinline__ void ldsm_x4(uint32_t* r, uint32_t addr) {
    asm volatile("ldmatrix.sync.aligned.m8n8.x4.shared.b16 {%0,%1,%2,%3}, [%4];"
                 : "=r"(r[0]), "=r"(r[1]), "=r"(r[2]), "=r"(r[3]) : "r"(addr));
}
__device__ __forceinline__ void mma16816(float* c, const uint32_t* a,
                                         uint32_t b0, uint32_t b1) {
    asm volatile("mma.sync.aligned.m16n8k16.row.col.f32.f16.f16.f32 "
                 "{%0,%1,%2,%3}, {%4,%5,%6,%7}, {%8,%9}, {%0,%1,%2,%3};"
                 : "+f"(c[0]), "+f"(c[1]), "+f"(c[2]), "+f"(c[3])
                 : "r"(a[0]), "r"(a[1]), "r"(a[2]), "r"(a[3]), "r"(b0), "r"(b1));
}
__device__ __forceinline__ void cp16(uint32_t saddr, const void* g, int src_sz) {
    asm volatile("cp.async.cg.shared.global [%0], [%1], 16, %2;"
                 :: "r"(saddr), "l"(g), "r"(src_sz) : "memory");
}
__device__ __forceinline__ void cp_commit() {
    asm volatile("cp.async.commit_group;" ::: "memory");
}
// ---- L2 eviction-priority via createpolicy + cache_hint ----
__device__ __forceinline__ uint64_t pol_evict_last() {
    uint64_t p;
    asm("createpolicy.fractional.L2::evict_last.b64 %0, 1.0;" : "=l"(p));
    return p;
}
__device__ __forceinline__ uint64_t pol_evict_first() {
    uint64_t p;
    asm("createpolicy.fractional.L2::evict_first.b64 %0, 1.0;" : "=l"(p));
    return p;
}
__device__ __forceinline__ uint4 ldg_hint_u4(const void* p, uint64_t pol) {
    uint4 v;
    asm volatile("ld.global.nc.L2::cache_hint.v4.u32 {%0,%1,%2,%3}, [%4], %5;"
                 : "=r"(v.x), "=r"(v.y), "=r"(v.z), "=r"(v.w) : "l"(p), "l"(pol));
    return v;
}
__device__ __forceinline__ float4 ldg_hint_f4(const void* p, uint64_t pol) {
    float4 v;
    asm volatile("ld.global.nc.L2::cache_hint.v4.f32 {%0,%1,%2,%3}, [%4], %5;"
                 : "=f"(v.x), "=f"(v.y), "=f"(v.z), "=f"(v.w) : "l"(p), "l"(pol));
    return v;
}
__device__ __forceinline__ void stg_hint_f4(void* p, float4 v, uint64_t pol) {
    asm volatile("st.global.L2::cache_hint.v4.f32 [%0], {%1,%2,%3,%4}, %5;"
                 :: "l"(p), "f"(v.x), "f"(v.y), "f"(v.z), "f"(v.w), "l"(pol)
                 : "memory");
}
__device__ __forceinline__ void stg_hint_f2(void* p, float2 v, uint64_t pol) {
    asm volatile("st.global.L2::cache_hint.v2.f32 [%0], {%1,%2}, %3;"
                 :: "l"(p), "f"(v.x), "f"(v.y), "l"(pol) : "memory");
}
__device__ __forceinline__ void stg_hint_u32(void* p, uint32_t v, uint64_t pol) {
    asm volatile("st.global.L2::cache_hint.u32 [%0], %1, %2;"
                 :: "l"(p), "r"(v), "l"(pol) : "memory");
}

// ============================= prep kernels (once) ==============================
__global__ void wprep_kernel(const float* __restrict__ W_in,
                             const float* __restrict__ W_out) {
    int idx = blockIdx.x * blockDim.x + threadIdx.x;
    if (idx >= 2 * 256 * 128) return;
    int layer = idx >> 15;
    int n = (idx >> 7) & 255;
    int k = idx & 127;
    const float* W = (layer ? W_out : W_in) + ((n >= 128) ? 128 * 128 : 0);
    float w = W[k * 128 + (n & 127)];
    __half w0 = __float2half_rn(w);
    __half w1 = __float2half_rn(w - __half2float(w0));
    g_B0[idx] = w0;
    g_B1[idx] = w1;
}
__global__ void xh_kernel(const float* __restrict__ x, int n4) {
    int i = blockIdx.x * blockDim.x + threadIdx.x;
    if (i >= n4) return;
    float4 v = ((const float4*)x)[i];
    __half2 t0 = __floats2half2_rn(v.x, v.y);
    __half2 t1 = __floats2half2_rn(v.z, v.w);
    uint2 p = make_uint2(*(uint32_t*)&t0, *(uint32_t*)&t1);
    ((uint2*)g_xh)[i] = p;
}

// =============================== CSR build ======================================
__global__ void zero_int_kernel(int* __restrict__ a, int n) {
    int i = blockIdx.x * blockDim.x + threadIdx.x;
    if (i < n) a[i] = 0;
}
__global__ void deg_kernel(const int* __restrict__ dst, int E) {
    int e = blockIdx.x * blockDim.x + threadIdx.x;
    if (e < E) atomicAdd(&g_deg[dst[e]], 1);
}
__global__ void scan_kernel(int n) {
    __shared__ int part[1024];
    const int T = 1024;
    int tid = threadIdx.x;
    int chunk = (n + T - 1) / T;
    int b = tid * chunk, e = min(b + chunk, n);
    int s = 0;
    for (int i = b; i < e; ++i) s += g_deg[i];
    part[tid] = s;
    __syncthreads();
    if (tid == 0) {
        int run = 0;
        for (int i = 0; i < T; ++i) { int t = part[i]; part[i] = run; run += t; }
    }
    __syncthreads();
    int run = part[tid];
    for (int i = b; i < e; ++i) { g_row_start[i] = run; run += g_deg[i]; }
    if (e == n) g_row_start[n] = run;
}
__global__ void fill_kernel(const int* __restrict__ src,
                            const int* __restrict__ dst, int E) {
    int e = blockIdx.x * blockDim.x + threadIdx.x;
    if (e < E) {
        int d = dst[e];
        int slot = g_row_start[d] + atomicSub(&g_deg[d], 1) - 1;
        g_csr[slot] = src[e];
    }
}

// ====== persistent mma.sync dual GEMM, cp.async double-buffered A ===============
#define GT 512
#define SM_A0  0                 // 32 KB
#define SM_A1  32768             // 32 KB
#define SM_BHI 65536             // 64 KB (256 rows)
#define SM_BLO 131072            // 32 KB (self half only)
#define SMEM_TOTAL_GEMM 163840

__device__ __forceinline__ void prefetch_A(uint32_t sb, int buf,
                                           const __half* __restrict__ feath,
                                           int row0, int nrows) {
    const uint32_t base = sb + (buf ? SM_A1 : SM_A0);
    int idx = threadIdx.x;
    #pragma unroll
    for (int j = 0; j < 4; ++j, idx += GT) {
        int r = idx >> 4, ch = idx & 15;
        int row = row0 + r;
        uint32_t off = r * 256 + ((ch ^ (r & 7)) << 4);
        cp16(base + off, feath + (size_t)row * 128 + ch * 8,
             (row < nrows) ? 16 : 0);
    }
}

__global__ __launch_bounds__(GT, 1)
void mma_gemm_kernel(const __half* __restrict__ feath,
                     const __half* __restrict__ Bg0,
                     const __half* __restrict__ Bg1,
                     float* __restrict__ out_self,
                     __half* __restrict__ out_msg,
                     int row_base, int nrows, int ntiles)
{
    extern __shared__ char smc[];
    const int tid = threadIdx.x;
    const uint32_t sb = sm_u32(smc);

    {
        int idx = tid;
        #pragma unroll
        for (int j = 0; j < 8; ++j, idx += GT) {
            int n = idx >> 4, ch = idx & 15;
            uint32_t off = n * 256 + ((ch ^ (n & 7)) << 4);
            cp16(sb + SM_BHI + off, Bg0 + n * 128 + ch * 8, 16);
        }
        idx = tid;
        #pragma unroll
        for (int j = 0; j < 4; ++j, idx += GT) {
            int n = idx >> 4, ch = idx & 15;
            uint32_t off = n * 256 + ((ch ^ (n & 7)) << 4);
            cp16(sb + SM_BLO + off, Bg1 + n * 128 + ch * 8, 16);
        }
    }
    int t = blockIdx.x;
    const int stride = gridDim.x;
    if (t < ntiles) prefetch_A(sb, 0, feath, row_base + t * 128, nrows);
    cp_commit();

    const int wid = tid >> 5, lane = tid & 31;
    const int mw = wid & 3;
    const int nw = wid >> 2;
    const bool self_half = (nw < 2);
    const int s3 = lane & 7, sel = lane >> 3;
    const int g = lane >> 2, tq = lane & 3;
    const int colhalf = (nw & 1) * 64;
    const uint64_t pL = pol_evict_last();
    const uint64_t pF = pol_evict_first();

    int cur = 0;
    for (; t < ntiles; t += stride, cur ^= 1) {
        const int row0 = row_base + t * 128;
        const int nt_tile = t + stride;
        const bool has_next = (nt_tile < ntiles);

        if (has_next) {
            prefetch_A(sb, cur ^ 1, feath, row_base + nt_tile * 128, nrows);
            cp_commit();
            asm volatile("cp.async.wait_group 1;" ::: "memory");
        } else {
            asm volatile("cp.async.wait_group 0;" ::: "memory");
        }
        __syncthreads();

        const uint32_t abase = sb + (cur ? SM_A1 : SM_A0);

        float acc[2][8][4];
        #pragma unroll
        for (int a = 0; a < 2; ++a)
            #pragma unroll
            for (int b = 0; b < 8; ++b)
                #pragma unroll
                for (int c = 0; c < 4; ++c) acc[a][b][c] = 0.f;

        #pragma unroll
        for (int ks = 0; ks < 8; ++ks) {
            uint32_t ahi[2][4];
            #pragma unroll
            for (int mt = 0; mt < 2; ++mt) {
                int r = mw * 32 + mt * 16 + s3 + ((sel & 1) << 3);
                int ch = 2 * ks + (sel >> 1);
                uint32_t off = r * 256 + ((ch ^ (r & 7)) << 4);
                ldsm_x4(ahi[mt], abase + off);
            }
            #pragma unroll
            for (int jp = 0; jp < 4; ++jp) {
                int r = nw * 64 + jp * 16 + s3 + ((sel >> 1) << 3);
                int ch = 2 * ks + (sel & 1);
                uint32_t off = r * 256 + ((ch ^ (r & 7)) << 4);
                uint32_t bhi[4], blo[4];
                ldsm_x4(bhi, sb + SM_BHI + off);
                if (self_half) ldsm_x4(blo, sb + SM_BLO + off);
                #pragma unroll
                for (int tt = 0; tt < 2; ++tt) {
                    int nt = jp * 2 + tt;
                    #pragma unroll
                    for (int mt = 0; mt < 2; ++mt) {
                        mma16816(acc[mt][nt], ahi[mt], bhi[2*tt], bhi[2*tt+1]);
                        if (self_half)
                            mma16816(acc[mt][nt], ahi[mt], blo[2*tt], blo[2*tt+1]);
                    }
                }
            }
        }

        // ---- epilogue: self -> evict_first stream; msg -> evict_last (reuse set)
        #pragma unroll
        for (int mt = 0; mt < 2; ++mt) {
            int rr = row0 + mw * 32 + mt * 16 + g;
            #pragma unroll
            for (int nt = 0; nt < 8; ++nt) {
                int col = colhalf + nt * 8 + 2 * tq;
                if (self_half) {
                    if (rr < nrows)
                        stg_hint_f2(out_self + (size_t)rr * 128 + col,
                                    make_float2(acc[mt][nt][0], acc[mt][nt][1]), pF);
                    if (rr + 8 < nrows)
                        stg_hint_f2(out_self + (size_t)(rr + 8) * 128 + col,
                                    make_float2(acc[mt][nt][2], acc[mt][nt][3]), pF);
                } else {
                    if (rr < nrows) {
                        __half2 h = __floats2half2_rn(acc[mt][nt][0], acc[mt][nt][1]);
                        stg_hint_u32(out_msg + (size_t)rr * 128 + col,
                                     *(uint32_t*)&h, pL);
                    }
                    if (rr + 8 < nrows) {
                        __half2 h = __floats2half2_rn(acc[mt][nt][2], acc[mt][nt][3]);
                        stg_hint_u32(out_msg + (size_t)(rr + 8) * 128 + col,
                                     *(uint32_t*)&h, pL);
                    }
                }
            }
        }
        __syncthreads();
    }
}

// ------- CSR gather-mean: 2 dst-nodes per warp, 16 lanes x LDG.128 per row ------
__global__ void agg_csr_kernel(const __half* __restrict__ msg,
                               const float* __restrict__ self,
                               float* __restrict__ outf,
                               __half* __restrict__ outh,
                               int node_base, int node_end, int relu)
{
    const int gwarp = (blockIdx.x * blockDim.x + threadIdx.x) >> 5;
    const int lane = threadIdx.x & 31;
    const int hw = lane >> 4;            // which of the 2 dsts this lane serves
    const int l16 = lane & 15;           // 16B chunk index within the 256B row
    const int w = node_base + gwarp * 2 + hw;
    if (w >= node_end) return;

    const uint64_t pL = pol_evict_last();
    const uint64_t pF = pol_evict_first();

    const int beg = __ldg(&g_row_start[w]);
    const int end = __ldg(&g_row_start[w + 1]);

    float acc[8];
    #pragma unroll
    for (int j = 0; j < 8; ++j) acc[j] = 0.f;

    int e = beg;
    for (; e + 8 <= end; e += 8) {       // 8 LDG.128 in flight per warp
        int s[8];
        #pragma unroll
        for (int j = 0; j < 8; ++j) s[j] = __ldg(&g_csr[e + j]);
        uint4 u[8];
        #pragma unroll
        for (int j = 0; j < 8; ++j)
            u[j] = ldg_hint_u4(msg + (size_t)s[j] * 128 + l16 * 8, pL);
        #pragma unroll
        for (int j = 0; j < 8; ++j) {
            float2 f;
            f = __half22float2(*(__half2*)&u[j].x); acc[0] += f.x; acc[1] += f.y;
            f = __half22float2(*(__half2*)&u[j].y); acc[2] += f.x; acc[3] += f.y;
            f = __half22float2(*(__half2*)&u[j].z); acc[4] += f.x; acc[5] += f.y;
            f = __half22float2(*(__half2*)&u[j].w); acc[6] += f.x; acc[7] += f.y;
        }
    }
    for (; e + 2 <= end; e += 2) {
        int s0 = __ldg(&g_csr[e]), s1 = __ldg(&g_csr[e + 1]);
        uint4 u0 = ldg_hint_u4(msg + (size_t)s0 * 128 + l16 * 8, pL);
        uint4 u1 = ldg_hint_u4(msg + (size_t)s1 * 128 + l16 * 8, pL);
        float2 f;
        f = __half22float2(*(__half2*)&u0.x); acc[0] += f.x; acc[1] += f.y;
        f = __half22float2(*(__half2*)&u0.y); acc[2] += f.x; acc[3] += f.y;
        f = __half22float2(*(__half2*)&u0.z); acc[4] += f.x; acc[5] += f.y;
        f = __half22float2(*(__half2*)&u0.w); acc[6] += f.x; acc[7] += f.y;
        f = __half22float2(*(__half2*)&u1.x); acc[0] += f.x; acc[1] += f.y;
        f = __half22float2(*(__half2*)&u1.y); acc[2] += f.x; acc[3] += f.y;
        f = __half22float2(*(__half2*)&u1.z); acc[4] += f.x; acc[5] += f.y;
        f = __half22float2(*(__half2*)&u1.w); acc[6] += f.x; acc[7] += f.y;
    }
    if (e < end) {
        int s0 = __ldg(&g_csr[e]);
        uint4 u0 = ldg_hint_u4(msg + (size_t)s0 * 128 + l16 * 8, pL);
        float2 f;
        f = __half22float2(*(__half2*)&u0.x); acc[0] += f.x; acc[1] += f.y;
        f = __half22float2(*(__half2*)&u0.y); acc[2] += f.x; acc[3] += f.y;
        f = __half22float2(*(__half2*)&u0.z); acc[4] += f.x; acc[5] += f.y;
        f = __half22float2(*(__half2*)&u0.w); acc[6] += f.x; acc[7] += f.y;
    }

    const float inv = 1.0f / fmaxf((float)(end - beg), 1.0f);
    const size_t base = (size_t)w * 128 + l16 * 8;
    float4 sf0 = ldg_hint_f4(self + base,     pF);
    float4 sf1 = ldg_hint_f4(self + base + 4, pF);
    float o[8];
    o[0] = fmaf(acc[0], inv, sf0.x); o[1] = fmaf(acc[1], inv, sf0.y);
    o[2] = fmaf(acc[2], inv, sf0.z); o[3] = fmaf(acc[3], inv, sf0.w);
    o[4] = fmaf(acc[4], inv, sf1.x); o[5] = fmaf(acc[5], inv, sf1.y);
    o[6] = fmaf(acc[6], inv, sf1.z); o[7] = fmaf(acc[7], inv, sf1.w);
    if (relu) {
        #pragma unroll
        for (int j = 0; j < 8; ++j) o[j] = fmaxf(o[j], 0.f);
    }
    if (outf) {
        stg_hint_f4(outf + base,     make_float4(o[0], o[1], o[2], o[3]), pF);
        stg_hint_f4(outf + base + 4, make_float4(o[4], o[5], o[6], o[7]), pF);
    } else {
        uint4 p;
        __half2 t;
        t = __floats2half2_rn(o[0], o[1]); p.x = *(uint32_t*)&t;
        t = __floats2half2_rn(o[2], o[3]); p.y = *(uint32_t*)&t;
        t = __floats2half2_rn(o[4], o[5]); p.z = *(uint32_t*)&t;
        t = __floats2half2_rn(o[6], o[7]); p.w = *(uint32_t*)&t;
        *(uint4*)(outh + base) = p;
    }
}

// --------------------------------------------------------------------------------
extern "C" void kernel_launch(void* const* d_in, const int* in_sizes, int n_in,
                              void* d_out, int out_size)
{
    const float* x     = (const float*)d_in[0];
    const float* W_in  = (const float*)d_in[1];
    const float* W_out = (const float*)d_in[2];
    const int*   src   = (const int*)d_in[3];
    const int*   dst   = (const int*)d_in[4];
    float*       out   = (float*)d_out;

    const int N = in_sizes[0] / FEAT;
    const int E = in_sizes[3];
    const int Nh = ((N / 2 + 127) / 128) * 128;

    float *p_self, *p_self2;
    __half *p_msg, *p_msg2, *p_hh, *p_xh;
    int *p_deg;
    __half *p_B0, *p_B1;
    cudaGetSymbolAddress((void**)&p_self,  g_self);
    cudaGetSymbolAddress((void**)&p_self2, g_self2);
    cudaGetSymbolAddress((void**)&p_msg,   g_msg);
    cudaGetSymbolAddress((void**)&p_msg2,  g_msg2);
    cudaGetSymbolAddress((void**)&p_hh,    g_hh);
    cudaGetSymbolAddress((void**)&p_xh,    g_xh);
    cudaGetSymbolAddress((void**)&p_deg,   g_deg);
    cudaGetSymbolAddress((void**)&p_B0,    g_B0);
    cudaGetSymbolAddress((void**)&p_B1,    g_B1);

    static bool s_init = false;
    static cudaStream_t s2 = 0;
    static cudaEvent_t evF = 0, evJ = 0, evA0 = 0, evG0 = 0;
    static int n_sm = 148;
    if (!s_init) {
        cudaFuncSetAttribute(mma_gemm_kernel,
                             cudaFuncAttributeMaxDynamicSharedMemorySize,
                             SMEM_TOTAL_GEMM);
        if (cudaStreamCreateWithFlags(&s2, cudaStreamNonBlocking) != cudaSuccess)
            s2 = 0;
        cudaEventCreateWithFlags(&evF,  cudaEventDisableTiming);
        cudaEventCreateWithFlags(&evJ,  cudaEventDisableTiming);
        cudaEventCreateWithFlags(&evA0, cudaEventDisableTiming);
        cudaEventCreateWithFlags(&evG0, cudaEventDisableTiming);
        cudaDeviceGetAttribute(&n_sm, cudaDevAttrMultiProcessorCount, 0);
        s_init = true;
    }

    const int egrid = (E + 255) / 256;
    const __half* B0L2 = p_B0 + 256 * 128;
    const __half* B1L2 = p_B1 + 256 * 128;

    // warps = ceil(nodes/2); 128-thread blocks = 4 warps = 8 nodes per block
    auto agg_grid = [](int nodes) { return (nodes + 7) / 8; };
    auto tiles = [](int rows) { return (rows + 127) / 128; };
    auto pgrid = [&](int nt) { return nt < n_sm ? nt : n_sm; };

    // ---- fork: CSR build on s2; default: wprep -> xh -> gemm1 (launch #4) ----
    cudaEventRecord(evF, 0);
    cudaStreamWaitEvent(s2, evF, 0);
    zero_int_kernel<<<(N + 255) / 256, 256, 0, s2>>>(p_deg, N);          // #1
    wprep_kernel<<<(2 * 256 * 128 + 255) / 256, 256>>>(W_in, W_out);     // #2
    xh_kernel<<<(N * 32 + 255) / 256, 256>>>(x, N * 32);                 // #3
    {
        int nt = tiles(N);
        mma_gemm_kernel<<<pgrid(nt), GT, SMEM_TOTAL_GEMM>>>(             // #4
            p_xh, p_B0, p_B1, p_self, p_msg, 0, N, nt);
    }
    deg_kernel<<<egrid, 256, 0, s2>>>(dst, E);
    scan_kernel<<<1, 1024, 0, s2>>>(N);
    fill_kernel<<<egrid, 256, 0, s2>>>(src, dst, E);
    cudaEventRecord(evJ, s2);

    // ---- layer 1 aggregation, chunked; h stored fp16 ----
    cudaStreamWaitEvent(0, evJ, 0);
    agg_csr_kernel<<<agg_grid(Nh), 128>>>(p_msg, p_self, nullptr, p_hh, 0, Nh, 1);
    cudaEventRecord(evA0, 0);

    // gemm2 chunk0 on s2, concurrent with agg1 chunk1 on default
    cudaStreamWaitEvent(s2, evA0, 0);
    {
        int nt = tiles(Nh);
        mma_gemm_kernel<<<pgrid(nt), GT, SMEM_TOTAL_GEMM, s2>>>(
            p_hh, B0L2, B1L2, p_self2, p_msg2, 0, N, nt);
    }
    cudaEventRecord(evG0, s2);

    agg_csr_kernel<<<agg_grid(N - Nh), 128>>>(p_msg, p_self, nullptr, p_hh, Nh, N, 1);
    {
        int nt = tiles(N - Nh);
        mma_gemm_kernel<<<pgrid(nt), GT, SMEM_TOTAL_GEMM>>>(
            p_hh, B0L2, B1L2, p_self2, p_msg2, Nh, N, nt);
    }

    // ---- layer 2 aggregation ----
    cudaStreamWaitEvent(0, evG0, 0);
    agg_csr_kernel<<<agg_grid(N), 128>>>(p_msg2, p_self2, out, nullptr, 0, N, 0);
}